// round 13
// baseline (speedup 1.0000x reference)
#include <cuda_runtime.h>
#include <cuda_fp16.h>
#include <math.h>
#include <stdint.h>

#define B_ 8
#define T_ 2048
#define C_ 2048
#define H_ 32
#define HS_ 64
#define M_ (B_*T_)   // 16384

typedef unsigned short ushort_t;

// ---------------- scratch (__device__ globals: allocation-free) ----------------
__device__ float g_tm [(size_t)M_*160];
__device__ float g_xr [(size_t)M_*C_];   // holds fp16 hi/lo split of xr
__device__ float g_xk [(size_t)M_*C_];   // holds fp16 hi/lo split of xk
__device__ float g_xv [(size_t)M_*C_];   // holds fp16 hi/lo split of xv
__device__ float g_xw [(size_t)M_*C_];
__device__ float g_xv2[(size_t)M_*C_];
__device__ float g_r  [(size_t)M_*C_];
__device__ float g_k  [(size_t)M_*C_];
__device__ float g_v  [(size_t)M_*C_];
__device__ float g_v2 [(size_t)M_*C_];
__device__ float g_d  [(size_t)M_*C_];
__device__ float g_lw [(size_t)M_*64];
__device__ float g_lv2[(size_t)M_*64];
__device__ float g_yw [(size_t)M_*C_];

// fp16 hi/lo split scratch (xv2 split, later yln split)
__device__ ushort_t g_ah[(size_t)M_*C_];
__device__ ushort_t g_al[(size_t)M_*C_];

// transposed fp16 weights: [N, K]
__device__ ushort_t g_wr[(size_t)C_*C_];
__device__ ushort_t g_wk[(size_t)C_*C_];
__device__ ushort_t g_wv[(size_t)C_*C_];
__device__ ushort_t g_wo[(size_t)C_*C_];

// ================= low-level helpers (base-target PTX only) =================
__device__ __forceinline__ uint32_t smem_u32(const void* p) {
    uint32_t a;
    asm("{ .reg .u64 t; cvta.to.shared.u64 t, %1; cvt.u32.u64 %0, t; }" : "=r"(a) : "l"(p));
    return a;
}
__device__ __forceinline__ void cp16(uint32_t dst, const void* src) {
    asm volatile("cp.async.cg.shared.global [%0], [%1], 16;" :: "r"(dst), "l"(src) : "memory");
}
#define CP_COMMIT() asm volatile("cp.async.commit_group;" ::: "memory")
#define CP_WAIT1()  asm volatile("cp.async.wait_group 1;"  ::: "memory")

__device__ __forceinline__ void ldsm_x4(uint32_t* r, uint32_t a) {
    asm volatile("ldmatrix.sync.aligned.m8n8.x4.shared.b16 {%0,%1,%2,%3}, [%4];"
        : "=r"(r[0]), "=r"(r[1]), "=r"(r[2]), "=r"(r[3]) : "r"(a));
}
__device__ __forceinline__ void mma16816h(float* c, const uint32_t* a, const uint32_t* b) {
    asm volatile("mma.sync.aligned.m16n8k16.row.col.f32.f16.f16.f32 "
        "{%0,%1,%2,%3}, {%4,%5,%6,%7}, {%8,%9}, {%0,%1,%2,%3};"
        : "+f"(c[0]), "+f"(c[1]), "+f"(c[2]), "+f"(c[3])
        : "r"(a[0]), "r"(a[1]), "r"(a[2]), "r"(a[3]), "r"(b[0]), "r"(b[1]));
}

__device__ __forceinline__ void split1(float v, ushort_t& h, ushort_t& l) {
    __half hb = __float2half_rn(v);
    h = __half_as_ushort(hb);
    l = __half_as_ushort(__float2half_rn(v - __half2float(hb)));
}

// ---------------- weight transpose + fp16 convert: T[n][k] = fp16(W[k][n]) ----------------
__global__ void __launch_bounds__(256) wsplit_t(
    const float* __restrict__ W, ushort_t* __restrict__ Th)
{
    __shared__ float ts[32][33];
    int n0 = blockIdx.x * 32, k0 = blockIdx.y * 32;
    int tx = threadIdx.x & 31, ty = threadIdx.x >> 5;
#pragma unroll
    for (int e = 0; e < 4; e++)
        ts[ty + 8*e][tx] = W[(size_t)(k0 + ty + 8*e)*C_ + n0 + tx];
    __syncthreads();
#pragma unroll
    for (int e = 0; e < 4; e++) {
        int n = ty + 8*e;
        Th[(size_t)(n0+n)*C_ + k0 + tx] =
            __half_as_ushort(__float2half_rn(ts[tx][n]));
    }
}

// ---------------- fp16x2 HMMA GEMM (unchanged from round 12) ----------------
#define LDB     80
#define SZ_A    (128*LDB)
#define SZ_B    (256*LDB)
#define STAGE_B (2*SZ_A + SZ_B)
#define NSTAGE  3
#define GEMM_SMEM (NSTAGE*STAGE_B)  // 122880

struct GemmBatch {
    const ushort_t* Ah[4];
    const ushort_t* Al[4];
    const ushort_t* Bh[4];
    float*          Cm[4];
};

__device__ __forceinline__ void gemm_load_stage(
    uint32_t sb, int s, const ushort_t* Ah, const ushort_t* Al,
    const ushort_t* Bh, int m0, int n0, int kt, int tid)
{
    int k0 = kt * 32;
    uint32_t base = sb + s*STAGE_B;
    {
        int row = tid >> 2, c = tid & 3;
        uint32_t d = base + row*LDB + c*16;
        size_t offA = (size_t)(m0 + row)*C_ + k0 + c*8;
        cp16(d,        Ah + offA);
        cp16(d + SZ_A, Al + offA);
    }
#pragma unroll
    for (int e = 0; e < 2; e++) {
        int q = tid + 512*e;
        int row = q >> 2, c = q & 3;
        uint32_t d = base + 2*SZ_A + row*LDB + c*16;
        size_t offB = (size_t)(n0 + row)*C_ + k0 + c*8;
        cp16(d, Bh + offB);
    }
    CP_COMMIT();
}

__device__ __forceinline__ void gemm_core(
    const ushort_t* __restrict__ Ah, const ushort_t* __restrict__ Al,
    const ushort_t* __restrict__ Bh, float* __restrict__ Cm, char* smem)
{
    uint32_t sb = smem_u32(smem);
    int tid = threadIdx.x, lane = tid & 31, w = tid >> 5;
    int wm = w & 3, wn = w >> 2;
    int m0 = blockIdx.y * 128, n0 = blockIdx.x * 256;

    float acc[2][8][4];
#pragma unroll
    for (int i = 0; i < 2; i++)
#pragma unroll
        for (int j = 0; j < 8; j++)
#pragma unroll
            for (int q = 0; q < 4; q++) acc[i][j][q] = 0.f;

    gemm_load_stage(sb, 0, Ah, Al, Bh, m0, n0, 0, tid);
    gemm_load_stage(sb, 1, Ah, Al, Bh, m0, n0, 1, tid);

    uint32_t a_off = (uint32_t)((wm*32 + (lane & 15))*LDB + (lane >> 4)*16);
    uint32_t b_off = (uint32_t)((wn*64 + (lane & 7) + ((lane >> 4) & 1)*8)*LDB
                                + ((lane >> 3) & 1)*16);

    for (int kt = 0; kt < C_/32; kt++) {
        int s = kt % NSTAGE;
        CP_WAIT1();
        __syncthreads();
        if (kt + 2 < C_/32)
            gemm_load_stage(sb, (kt+2) % NSTAGE, Ah, Al, Bh, m0, n0, kt+2, tid);

        uint32_t base = sb + s*STAGE_B;
#pragma unroll
        for (int kk = 0; kk < 2; kk++) {
            uint32_t ah[2][4], al[2][4], bb[4][4];
#pragma unroll
            for (int mt = 0; mt < 2; mt++) {
                uint32_t addr = base + a_off + mt*16*LDB + kk*32;
                ldsm_x4(ah[mt], addr);
                ldsm_x4(al[mt], addr + SZ_A);
            }
#pragma unroll
            for (int g = 0; g < 4; g++) {
                uint32_t addr = base + 2*SZ_A + b_off + g*16*LDB + kk*32;
                ldsm_x4(bb[g], addr);
            }
#pragma unroll
            for (int mt = 0; mt < 2; mt++)
#pragma unroll
                for (int nt = 0; nt < 8; nt++) {
                    const uint32_t* bp = &bb[nt >> 1][(nt & 1)*2];
                    mma16816h(acc[mt][nt], ah[mt], bp);
                    mma16816h(acc[mt][nt], al[mt], bp);
                }
        }
    }

#pragma unroll
    for (int mt = 0; mt < 2; mt++) {
        int r0 = m0 + wm*32 + mt*16 + (lane >> 2);
#pragma unroll
        for (int nt = 0; nt < 8; nt++) {
            int c0 = n0 + wn*64 + nt*8 + (lane & 3)*2;
            *(float2*)&Cm[(size_t)r0*C_ + c0] =
                make_float2(acc[mt][nt][0], acc[mt][nt][1]);
            *(float2*)&Cm[(size_t)(r0+8)*C_ + c0] =
                make_float2(acc[mt][nt][2], acc[mt][nt][3]);
        }
    }
}

__global__ void __launch_bounds__(512, 1) gemm_bf3b(GemmBatch gb)
{
    extern __shared__ char smem[];
    int z = blockIdx.z;
    gemm_core(gb.Ah[z], gb.Al[z], gb.Bh[z], gb.Cm[z], smem);
}

__global__ void __launch_bounds__(512, 1) gemm_bf3(
    const ushort_t* __restrict__ Ah, const ushort_t* __restrict__ Al,
    const ushort_t* __restrict__ Bh, float* __restrict__ Cm)
{
    extern __shared__ char smem[];
    gemm_core(Ah, Al, Bh, Cm, smem);
}

// ---------------- skinny GEMM + tanh (device body + wrappers) ----------------
template<int NS, bool FUSE>
__device__ __forceinline__ void skinny_body(
    const float* __restrict__ A, const float* __restrict__ W,
    float* __restrict__ out,
    const float* __restrict__ shift, const float* __restrict__ maax)
{
    __shared__ float As[32*68];
    __shared__ float Ws[32*NS];
    const int tid = threadIdx.x;
    const int m0  = blockIdx.x * 64;
    const int row = tid >> 2;
    const int cg  = tid & 3;

    float acc[NS/4];
#pragma unroll
    for (int i = 0; i < NS/4; i++) acc[i] = 0.f;

    for (int k0 = 0; k0 < C_; k0 += 32) {
#pragma unroll
        for (int e = 0; e < 2; e++) {
            int q  = tid + 256*e;
            int r  = q >> 3;
            int c4 = (q & 7) * 4;
            int m  = m0 + r;
            float4 val;
            if (FUSE) {
                float4 xv = *(const float4*)(A + (size_t)m*C_ + k0 + c4);
                int t = m & (T_-1);
                int b = m >> 11;
                float4 xp = (t > 0) ? *(const float4*)(A + (size_t)(m-1)*C_ + k0 + c4)
                                    : *(const float4*)(shift + (size_t)b*C_ + k0 + c4);
                float4 mx = *(const float4*)(maax + k0 + c4);
                val.x = xv.x + (xp.x - xv.x)*mx.x;
                val.y = xv.y + (xp.y - xv.y)*mx.y;
                val.z = xv.z + (xp.z - xv.z)*mx.z;
                val.w = xv.w + (xp.w - xv.w)*mx.w;
            } else {
                val = *(const float4*)(A + (size_t)m*C_ + k0 + c4);
            }
            As[(c4+0)*68 + r] = val.x;
            As[(c4+1)*68 + r] = val.y;
            As[(c4+2)*68 + r] = val.z;
            As[(c4+3)*68 + r] = val.w;
        }
        {
            const float4* src = (const float4*)(W + (size_t)k0*NS);
            for (int q = tid; q < 32*NS/4; q += 256)
                ((float4*)Ws)[q] = src[q];
        }
        __syncthreads();
#pragma unroll 8
        for (int k = 0; k < 32; k++) {
            float a = As[k*68 + row];
            const float* wrow = Ws + k*NS + cg*(NS/4);
#pragma unroll
            for (int j = 0; j < NS/16; j++) {
                float4 w4 = *(const float4*)(wrow + j*4);
                acc[j*4+0] = fmaf(a, w4.x, acc[j*4+0]);
                acc[j*4+1] = fmaf(a, w4.y, acc[j*4+1]);
                acc[j*4+2] = fmaf(a, w4.z, acc[j*4+2]);
                acc[j*4+3] = fmaf(a, w4.w, acc[j*4+3]);
            }
        }
        __syncthreads();
    }
    float* orow = out + (size_t)(m0+row)*NS + cg*(NS/4);
#pragma unroll
    for (int i = 0; i < NS/4; i++) orow[i] = tanhf(acc[i]);
}

__global__ void __launch_bounds__(256) skinny160_fuse(
    const float* A, const float* W, float* out,
    const float* shift, const float* maax)
{
    skinny_body<160, true>(A, W, out, shift, maax);
}

struct Skinny2 {
    const float* A[2];
    const float* W[2];
    float*       out[2];
};
__global__ void __launch_bounds__(256) skinny64_b(Skinny2 p)
{
    int z = blockIdx.y;
    skinny_body<64, false>(p.A[z], p.W[z], p.out[z], nullptr, nullptr);
}

// ---------------- 5-way mix apply (device body + wrappers) ----------------
// MODE 0: fp16 hi/lo split only.  MODE 1: fp32 only.  MODE 2: fp32 + split.
template<int MODE>
__device__ __forceinline__ void mix_body(
    const float* __restrict__ x, const float* __restrict__ shift,
    const float* __restrict__ tm, const float* __restrict__ w2,
    const float* __restrict__ maa,
    ushort_t* __restrict__ oh, ushort_t* __restrict__ ol,
    float* __restrict__ of, int f)
{
    __shared__ float tmf[32*32];
    __shared__ float w2f[32*64];
    int tid = threadIdx.x;
    int m0 = blockIdx.y * 32;
    int c0 = blockIdx.x * 64;
    {
        int r = tid >> 3, c4 = (tid & 7) * 4;
        *(float4*)&tmf[r*32 + c4] =
            *(const float4*)(tm + (size_t)(m0+r)*160 + f*32 + c4);
    }
#pragma unroll
    for (int e = 0; e < 2; e++) {
        int q = tid + 256*e;
        int d = q >> 4, c4 = (q & 15) * 4;
        *(float4*)&w2f[d*64 + c4] =
            *(const float4*)(w2 + (size_t)(f*32+d)*C_ + c0 + c4);
    }
    __syncthreads();
#pragma unroll
    for (int e = 0; e < 2; e++) {
        int p = tid + 256*e;
        int r  = p >> 4;
        int c4 = (p & 15) * 4;
        int m = m0 + r;
        int c = c0 + c4;
        float4 acc = make_float4(0.f,0.f,0.f,0.f);
#pragma unroll
        for (int d = 0; d < 32; d++) {
            float tv = tmf[r*32 + d];
            float4 w4 = *(const float4*)&w2f[d*64 + c4];
            acc.x = fmaf(tv, w4.x, acc.x);
            acc.y = fmaf(tv, w4.y, acc.y);
            acc.z = fmaf(tv, w4.z, acc.z);
            acc.w = fmaf(tv, w4.w, acc.w);
        }
        float4 xv = *(const float4*)(x + (size_t)m*C_ + c);
        int t = m & (T_-1), b = m >> 11;
        float4 xp = (t > 0) ? *(const float4*)(x + (size_t)(m-1)*C_ + c)
                            : *(const float4*)(shift + (size_t)b*C_ + c);
        float4 ma = *(const float4*)(maa + c);
        float4 o;
        o.x = xv.x + (xp.x - xv.x)*(ma.x + acc.x);
        o.y = xv.y + (xp.y - xv.y)*(ma.y + acc.y);
        o.z = xv.z + (xp.z - xv.z)*(ma.z + acc.z);
        o.w = xv.w + (xp.w - xv.w)*(ma.w + acc.w);
        size_t base = (size_t)m*C_ + c;
        if (MODE == 1 || MODE == 2)
            *(float4*)(of + base) = o;
        if (MODE == 0 || MODE == 2) {
            ushort4 h4, l4;
            split1(o.x, h4.x, l4.x);
            split1(o.y, h4.y, l4.y);
            split1(o.z, h4.z, l4.z);
            split1(o.w, h4.w, l4.w);
            *(ushort4*)(oh + base) = h4;
            *(ushort4*)(ol + base) = l4;
        }
    }
}

struct MixB {
    const float* maa[3];
    ushort_t*    oh[3];
    ushort_t*    ol[3];
};
__global__ void __launch_bounds__(256) mix_apply3(
    const float* x, const float* shift, const float* tm, const float* w2,
    MixB mb)
{
    int f = blockIdx.z;
    mix_body<0>(x, shift, tm, w2, mb.maa[f], mb.oh[f], mb.ol[f], nullptr, f);
}
template<int MODE>
__global__ void __launch_bounds__(256) mix_apply_f(
    const float* x, const float* shift, const float* tm, const float* w2,
    const float* maa, ushort_t* oh, ushort_t* ol, float* of, int f)
{
    mix_body<MODE>(x, shift, tm, w2, maa, oh, ol, of, f);
}

// ---------------- small-K GEMM (K=64) with fused epilogues ----------------
template<int MODE>
__global__ void __launch_bounds__(256) smallk_gemm(
    const float* __restrict__ A, const float* __restrict__ W,
    const float* __restrict__ td, float* __restrict__ out1)
{
    __shared__ float As[32*64];
    __shared__ float Ws[64*128];
    int tid = threadIdx.x;
    int m0 = blockIdx.y * 32, c0 = blockIdx.x * 128;
    {
        const float4* src = (const float4*)(A + (size_t)m0*64);
#pragma unroll
        for (int q = tid; q < 512; q += 256) ((float4*)As)[q] = src[q];
    }
#pragma unroll
    for (int e = 0; e < 8; e++) {
        int q = tid + 256*e;
        int kr = q >> 5, c4 = (q & 31) * 4;
        *(float4*)&Ws[kr*128 + c4] = *(const float4*)(W + (size_t)kr*C_ + c0 + c4);
    }
    __syncthreads();
    int ty = tid >> 4, tx = tid & 15;
    int r0 = ty * 2;
    float acc[2][8];
#pragma unroll
    for (int i = 0; i < 2; i++)
#pragma unroll
        for (int j = 0; j < 8; j++) acc[i][j] = 0.f;
#pragma unroll
    for (int k = 0; k < 64; k++) {
        float a0 = As[r0*64 + k];
        float a1 = As[(r0+1)*64 + k];
        float4 b0 = *(const float4*)&Ws[k*128 + tx*8];
        float4 b1 = *(const float4*)&Ws[k*128 + tx*8 + 4];
        float bv[8] = {b0.x,b0.y,b0.z,b0.w,b1.x,b1.y,b1.z,b1.w};
#pragma unroll
        for (int j = 0; j < 8; j++) {
            acc[0][j] = fmaf(a0, bv[j], acc[0][j]);
            acc[1][j] = fmaf(a1, bv[j], acc[1][j]);
        }
    }
#pragma unroll
    for (int rr = 0; rr < 2; rr++) {
        int m = m0 + r0 + rr;
        size_t base = (size_t)m*C_ + c0 + tx*8;
        if (MODE == 0) {
#pragma unroll
            for (int j = 0; j < 8; j++) {
                float w = td[c0 + tx*8 + j] + acc[rr][j];
                out1[base + j] = expf(-expf(w));
            }
        } else {
#pragma unroll
            for (int j = 0; j < 8; j++) out1[base + j] += acc[rr][j];
        }
    }
}

// ---------------- WKV scan: 256 threads, 4-way k-split + quad shfl reduce ----------------
// thread (j, ig): j = tid>>2 (output column), ig = tid&3 (16-row slice of k-dim).
// skd[j] = (r_j, k_j*(1-d_j), d_j, v_j) written by ig==0 threads.
__global__ void __launch_bounds__(256) wkv_scan(
    const float* __restrict__ rp, const float* __restrict__ kp,
    const float* __restrict__ vp, const float* __restrict__ dp,
    const float* __restrict__ S0, float* __restrict__ yp,
    float* __restrict__ Sout)
{
    int bh = blockIdx.x;
    int tid = threadIdx.x;
    int j  = tid >> 2;      // 0..63
    int ig = tid & 3;       // 0..3
    int b = bh >> 5, h = bh & (H_-1);

    float S[16];
    {
        const float* s0 = S0 + (size_t)bh*HS_*HS_ + (size_t)(ig*16)*64 + j;
#pragma unroll
        for (int ii = 0; ii < 16; ii++) S[ii] = s0[(size_t)ii*64];
    }
    __shared__ float4 skd[64];
    size_t idx = (size_t)b*T_*C_ + (size_t)h*64 + j;

    float rr = 0.f, kk = 0.f, dd = 0.f, vv = 0.f;
    if (ig == 0) { rr = rp[idx]; kk = kp[idx]; dd = dp[idx]; vv = vp[idx]; }

    for (int t = 0; t < T_; t++) {
        float rn = 0.f, kn = 0.f, dn = 0.f, vn = 0.f;
        if (ig == 0 && t + 1 < T_) {
            size_t nx = idx + C_;
            rn = rp[nx]; kn = kp[nx]; dn = dp[nx]; vn = vp[nx];
        }
        if (ig == 0)
            skd[j] = make_float4(rr, kk * (1.0f - dd), dd, vv);
        __syncthreads();
        float vj = skd[j].w;
        float acc = 0.f;
#pragma unroll
        for (int ii = 0; ii < 16; ii++) {
            float4 q = skd[ig*16 + ii];
            acc   = fmaf(q.x, S[ii], acc);
            S[ii] = fmaf(q.z, S[ii], q.y * vj);
        }
        acc += __shfl_xor_sync(0xffffffffu, acc, 1);
        acc += __shfl_xor_sync(0xffffffffu, acc, 2);
        if (ig == 0) yp[idx] = acc;
        __syncthreads();
        idx += C_;
        rr = rn; kk = kn; dd = dn; vv = vn;
    }
    {
        float* so = Sout + (size_t)bh*HS_*HS_ + (size_t)(ig*16)*64 + j;
#pragma unroll
        for (int ii = 0; ii < 16; ii++) so[(size_t)ii*64] = S[ii];
    }
}

// ---------------- fused add + LayerNorm, emits fp16 hi/lo split ----------------
__global__ void __launch_bounds__(256) ln_add_split(
    const float* __restrict__ a, const float* __restrict__ b,
    const float* __restrict__ lw, const float* __restrict__ lb,
    ushort_t* __restrict__ oh, ushort_t* __restrict__ ol)
{
    int m = blockIdx.x;
    int tid = threadIdx.x;
    const float* ar = a + (size_t)m*C_;
    const float* br = b + (size_t)m*C_;
    float vals[8];
    float s = 0.f, s2 = 0.f;
#pragma unroll
    for (int i = 0; i < 8; i++) {
        int c = tid + 256*i;
        float u = ar[c] + br[c];
        vals[i] = u; s += u; s2 = fmaf(u, u, s2);
    }
#pragma unroll
    for (int o = 16; o > 0; o >>= 1) {
        s  += __shfl_xor_sync(0xffffffffu, s,  o);
        s2 += __shfl_xor_sync(0xffffffffu, s2, o);
    }
    __shared__ float sa[8], sb2[8];
    if ((tid & 31) == 0) { sa[tid>>5] = s; sb2[tid>>5] = s2; }
    __syncthreads();
    s = 0.f; s2 = 0.f;
#pragma unroll
    for (int i = 0; i < 8; i++) { s += sa[i]; s2 += sb2[i]; }
    float mu  = s * (1.0f/C_);
    float var = s2 * (1.0f/C_) - mu*mu;
    float inv = rsqrtf(var + 1e-5f);
#pragma unroll
    for (int i = 0; i < 8; i++) {
        int c = tid + 256*i;
        float v = (vals[i] - mu)*inv*lw[c] + lb[c];
        ushort_t h, l;
        split1(v, h, l);
        oh[(size_t)m*C_ + c] = h;
        ol[(size_t)m*C_ + c] = l;
    }
}

__global__ void copy_xlast(const float* __restrict__ x, float* __restrict__ o)
{
    int i = blockIdx.x*256 + threadIdx.x;
    int b = i >> 11, c = i & (C_-1);
    o[i] = x[((size_t)b*T_ + (T_-1))*C_ + c];
}

// ---------------- launcher ----------------
extern "C" void kernel_launch(void* const* d_in, const int* in_sizes, int n_in,
                              void* d_out, int out_size)
{
    (void)in_sizes; (void)n_in;
    const float* x     = (const float*)d_in[0];
    const float* shift = (const float*)d_in[1];
    const float* wkv0  = (const float*)d_in[2];
    const float* maax  = (const float*)d_in[3];
    const float* maar  = (const float*)d_in[4];
    const float* maak  = (const float*)d_in[5];
    const float* maav  = (const float*)d_in[6];
    const float* maaw  = (const float*)d_in[7];
    const float* maav2 = (const float*)d_in[8];
    const float* w1    = (const float*)d_in[9];
    const float* w2    = (const float*)d_in[10];
    const float* tdec  = (const float*)d_in[11];
    const float* dw1   = (const float*)d_in[12];
    const float* dw2   = (const float*)d_in[13];
    const float* vw1   = (const float*)d_in[14];
    const float* vw2   = (const float*)d_in[15];
    const float* Wr    = (const float*)d_in[17];
    const float* Wk    = (const float*)d_in[18];
    const float* Wv    = (const float*)d_in[19];
    const float* Wo    = (const float*)d_in[20];
    const float* lnw   = (const float*)d_in[21];
    const float* lnb   = (const float*)d_in[22];
    float* out = (float*)d_out;

    float *tm,*xrf,*xkf,*xvf,*xw,*xv2,*rb,*kb,*vb,*v2b,*db,*lwv,*lv2,*yw;
    ushort_t *ah,*al,*wr,*wk,*wv,*wo;
    cudaGetSymbolAddress((void**)&tm,  g_tm);
    cudaGetSymbolAddress((void**)&xrf, g_xr);
    cudaGetSymbolAddress((void**)&xkf, g_xk);
    cudaGetSymbolAddress((void**)&xvf, g_xv);
    cudaGetSymbolAddress((void**)&xw,  g_xw);
    cudaGetSymbolAddress((void**)&xv2, g_xv2);
    cudaGetSymbolAddress((void**)&rb,  g_r);
    cudaGetSymbolAddress((void**)&kb,  g_k);
    cudaGetSymbolAddress((void**)&vb,  g_v);
    cudaGetSymbolAddress((void**)&v2b, g_v2);
    cudaGetSymbolAddress((void**)&db,  g_d);
    cudaGetSymbolAddress((void**)&lwv, g_lw);
    cudaGetSymbolAddress((void**)&lv2, g_lv2);
    cudaGetSymbolAddress((void**)&yw,  g_yw);
    cudaGetSymbolAddress((void**)&ah,  g_ah);
    cudaGetSymbolAddress((void**)&al,  g_al);
    cudaGetSymbolAddress((void**)&wr,  g_wr);
    cudaGetSymbolAddress((void**)&wk,  g_wk);
    cudaGetSymbolAddress((void**)&wv,  g_wv);
    cudaGetSymbolAddress((void**)&wo,  g_wo);

    ushort_t* xrh = (ushort_t*)xrf; ushort_t* xrl = xrh + (size_t)M_*C_;
    ushort_t* xkh = (ushort_t*)xkf; ushort_t* xkl = xkh + (size_t)M_*C_;
    ushort_t* xvh = (ushort_t*)xvf; ushort_t* xvl = xvh + (size_t)M_*C_;

    cudaFuncSetAttribute(gemm_bf3,  cudaFuncAttributeMaxDynamicSharedMemorySize, GEMM_SMEM);
    cudaFuncSetAttribute(gemm_bf3b, cudaFuncAttributeMaxDynamicSharedMemorySize, GEMM_SMEM);

    // 0) weight transpose + fp16 convert
    {
        dim3 gt(C_/32, C_/32);
        wsplit_t<<<gt,256>>>(Wr, wr);
        wsplit_t<<<gt,256>>>(Wk, wk);
        wsplit_t<<<gt,256>>>(Wv, wv);
        wsplit_t<<<gt,256>>>(Wo, wo);
    }

    // 1) LoRA-5 projection with fused token-shift mixing
    skinny160_fuse<<<M_/64, 256>>>(x, w1, tm, shift, maax);

    // 2) 5-way mix: z-batched MODE0 (r,k,v) + xw fp32 + xv2 both
    {
        dim3 g3(C_/64, M_/32, 3);
        MixB mb;
        mb.maa[0]=maar; mb.oh[0]=xrh; mb.ol[0]=xrl;
        mb.maa[1]=maak; mb.oh[1]=xkh; mb.ol[1]=xkl;
        mb.maa[2]=maav; mb.oh[2]=xvh; mb.ol[2]=xvl;
        mix_apply3<<<g3,256>>>(x, shift, tm, w2, mb);
        dim3 g(C_/64, M_/32);
        mix_apply_f<1><<<g,256>>>(x, shift, tm, w2, maaw,  nullptr, nullptr, xw, 3);
        mix_apply_f<2><<<g,256>>>(x, shift, tm, w2, maav2, ah, al, xv2, 4);
    }

    // 3) big projections via batched HMMA fp16x2 (z = r, k, v, v2)
    {
        GemmBatch gb;
        gb.Ah[0]=xrh; gb.Al[0]=xrl; gb.Bh[0]=wr; gb.Cm[0]=rb;
        gb.Ah[1]=xkh; gb.Al[1]=xkl; gb.Bh[1]=wk; gb.Cm[1]=kb;
        gb.Ah[2]=xvh; gb.Al[2]=xvl; gb.Bh[2]=wv; gb.Cm[2]=vb;
        gb.Ah[3]=ah;  gb.Al[3]=al;  gb.Bh[3]=wv; gb.Cm[3]=v2b;
        dim3 gb4(C_/256, M_/128, 4);
        gemm_bf3b<<<gb4,512,GEMM_SMEM>>>(gb);
    }

    // 4) decay / value2 LoRAs (batched skinny) + smallK epilogues
    {
        Skinny2 sp;
        sp.A[0]=xw;  sp.W[0]=dw1; sp.out[0]=lwv;
        sp.A[1]=xv2; sp.W[1]=vw1; sp.out[1]=lv2;
        dim3 gsk(M_/64, 2);
        skinny64_b<<<gsk,256>>>(sp);
        dim3 gs(C_/128, M_/32);
        smallk_gemm<0><<<gs,256>>>(lwv, dw2, tdec, db);      // d only
        smallk_gemm<1><<<gs,256>>>(lv2, vw2, nullptr, v2b);  // v2 += lora
    }

    // 5) WKV scan (256 threads, k*(1-d) inline), 6) LN, 7) output projection
    const size_t OFFS = (size_t)M_*C_;
    const size_t OFFX = OFFS + (size_t)B_*H_*HS_*HS_;
    bool full = (size_t)out_size >= OFFX + (size_t)B_*C_;
    float* Sout = full ? (out + OFFS) : tm;
    wkv_scan<<<B_*H_, 256>>>(rb, kb, vb, db, wkv0, yw, Sout);
    ln_add_split<<<M_, 256>>>(yw, v2b, lnw, lnb, ah, al);
    dim3 gg(C_/256, M_/128);
    gemm_bf3<<<gg,512,GEMM_SMEM>>>(ah, al, wo, out);
    if (full) copy_xlast<<<(B_*C_)/256, 256>>>(x, out + OFFX);
}

// round 14
// speedup vs baseline: 1.3799x; 1.3799x over previous
#include <cuda_runtime.h>
#include <cuda_fp16.h>
#include <math.h>
#include <stdint.h>

#define B_ 8
#define T_ 2048
#define C_ 2048
#define H_ 32
#define HS_ 64
#define M_ (B_*T_)   // 16384

typedef unsigned short ushort_t;

// ---------------- scratch (__device__ globals: allocation-free) ----------------
__device__ float g_tm [(size_t)M_*160];
__device__ float g_xr [(size_t)M_*C_];   // holds fp16 hi/lo split of xr
__device__ float g_xk [(size_t)M_*C_];   // holds fp16 hi/lo split of xk
__device__ float g_xv [(size_t)M_*C_];   // holds fp16 hi/lo split of xv
__device__ float g_xw [(size_t)M_*C_];
__device__ float g_xv2[(size_t)M_*C_];
__device__ float g_r  [(size_t)M_*C_];
__device__ float g_k  [(size_t)M_*C_];
__device__ float g_v  [(size_t)M_*C_];
__device__ float g_v2 [(size_t)M_*C_];
__device__ float g_d  [(size_t)M_*C_];
__device__ float g_lw [(size_t)M_*64];
__device__ float g_lv2[(size_t)M_*64];
__device__ float g_yw [(size_t)M_*C_];

// fp16 hi/lo split scratch (xv2 split, later yln split)
__device__ ushort_t g_ah[(size_t)M_*C_];
__device__ ushort_t g_al[(size_t)M_*C_];

// transposed fp16 weights: [N, K]
__device__ ushort_t g_wr[(size_t)C_*C_];
__device__ ushort_t g_wk[(size_t)C_*C_];
__device__ ushort_t g_wv[(size_t)C_*C_];
__device__ ushort_t g_wo[(size_t)C_*C_];

// ================= low-level helpers (base-target PTX only) =================
__device__ __forceinline__ uint32_t smem_u32(const void* p) {
    uint32_t a;
    asm("{ .reg .u64 t; cvta.to.shared.u64 t, %1; cvt.u32.u64 %0, t; }" : "=r"(a) : "l"(p));
    return a;
}
__device__ __forceinline__ void cp16(uint32_t dst, const void* src) {
    asm volatile("cp.async.cg.shared.global [%0], [%1], 16;" :: "r"(dst), "l"(src) : "memory");
}
#define CP_COMMIT() asm volatile("cp.async.commit_group;" ::: "memory")
#define CP_WAIT1()  asm volatile("cp.async.wait_group 1;"  ::: "memory")

__device__ __forceinline__ void ldsm_x4(uint32_t* r, uint32_t a) {
    asm volatile("ldmatrix.sync.aligned.m8n8.x4.shared.b16 {%0,%1,%2,%3}, [%4];"
        : "=r"(r[0]), "=r"(r[1]), "=r"(r[2]), "=r"(r[3]) : "r"(a));
}
__device__ __forceinline__ void mma16816h(float* c, const uint32_t* a, const uint32_t* b) {
    asm volatile("mma.sync.aligned.m16n8k16.row.col.f32.f16.f16.f32 "
        "{%0,%1,%2,%3}, {%4,%5,%6,%7}, {%8,%9}, {%0,%1,%2,%3};"
        : "+f"(c[0]), "+f"(c[1]), "+f"(c[2]), "+f"(c[3])
        : "r"(a[0]), "r"(a[1]), "r"(a[2]), "r"(a[3]), "r"(b[0]), "r"(b[1]));
}

__device__ __forceinline__ void split1(float v, ushort_t& h, ushort_t& l) {
    __half hb = __float2half_rn(v);
    h = __half_as_ushort(hb);
    l = __half_as_ushort(__float2half_rn(v - __half2float(hb)));
}

// ---------------- weight transpose + fp16 convert: T[n][k] = fp16(W[k][n]) ----------------
__global__ void __launch_bounds__(256) wsplit_t(
    const float* __restrict__ W, ushort_t* __restrict__ Th)
{
    __shared__ float ts[32][33];
    int n0 = blockIdx.x * 32, k0 = blockIdx.y * 32;
    int tx = threadIdx.x & 31, ty = threadIdx.x >> 5;
#pragma unroll
    for (int e = 0; e < 4; e++)
        ts[ty + 8*e][tx] = W[(size_t)(k0 + ty + 8*e)*C_ + n0 + tx];
    __syncthreads();
#pragma unroll
    for (int e = 0; e < 4; e++) {
        int n = ty + 8*e;
        Th[(size_t)(n0+n)*C_ + k0 + tx] =
            __half_as_ushort(__float2half_rn(ts[tx][n]));
    }
}

// ---------------- fp16x2 HMMA GEMM (round-12 proven) ----------------
#define LDB     80
#define SZ_A    (128*LDB)
#define SZ_B    (256*LDB)
#define STAGE_B (2*SZ_A + SZ_B)
#define NSTAGE  3
#define GEMM_SMEM (NSTAGE*STAGE_B)  // 122880

struct GemmBatch {
    const ushort_t* Ah[4];
    const ushort_t* Al[4];
    const ushort_t* Bh[4];
    float*          Cm[4];
};

__device__ __forceinline__ void gemm_load_stage(
    uint32_t sb, int s, const ushort_t* Ah, const ushort_t* Al,
    const ushort_t* Bh, int m0, int n0, int kt, int tid)
{
    int k0 = kt * 32;
    uint32_t base = sb + s*STAGE_B;
    {
        int row = tid >> 2, c = tid & 3;
        uint32_t d = base + row*LDB + c*16;
        size_t offA = (size_t)(m0 + row)*C_ + k0 + c*8;
        cp16(d,        Ah + offA);
        cp16(d + SZ_A, Al + offA);
    }
#pragma unroll
    for (int e = 0; e < 2; e++) {
        int q = tid + 512*e;
        int row = q >> 2, c = q & 3;
        uint32_t d = base + 2*SZ_A + row*LDB + c*16;
        size_t offB = (size_t)(n0 + row)*C_ + k0 + c*8;
        cp16(d, Bh + offB);
    }
    CP_COMMIT();
}

__device__ __forceinline__ void gemm_core(
    const ushort_t* __restrict__ Ah, const ushort_t* __restrict__ Al,
    const ushort_t* __restrict__ Bh, float* __restrict__ Cm, char* smem)
{
    uint32_t sb = smem_u32(smem);
    int tid = threadIdx.x, lane = tid & 31, w = tid >> 5;
    int wm = w & 3, wn = w >> 2;
    int m0 = blockIdx.y * 128, n0 = blockIdx.x * 256;

    float acc[2][8][4];
#pragma unroll
    for (int i = 0; i < 2; i++)
#pragma unroll
        for (int j = 0; j < 8; j++)
#pragma unroll
            for (int q = 0; q < 4; q++) acc[i][j][q] = 0.f;

    gemm_load_stage(sb, 0, Ah, Al, Bh, m0, n0, 0, tid);
    gemm_load_stage(sb, 1, Ah, Al, Bh, m0, n0, 1, tid);

    uint32_t a_off = (uint32_t)((wm*32 + (lane & 15))*LDB + (lane >> 4)*16);
    uint32_t b_off = (uint32_t)((wn*64 + (lane & 7) + ((lane >> 4) & 1)*8)*LDB
                                + ((lane >> 3) & 1)*16);

    for (int kt = 0; kt < C_/32; kt++) {
        int s = kt % NSTAGE;
        CP_WAIT1();
        __syncthreads();
        if (kt + 2 < C_/32)
            gemm_load_stage(sb, (kt+2) % NSTAGE, Ah, Al, Bh, m0, n0, kt+2, tid);

        uint32_t base = sb + s*STAGE_B;
#pragma unroll
        for (int kk = 0; kk < 2; kk++) {
            uint32_t ah[2][4], al[2][4], bb[4][4];
#pragma unroll
            for (int mt = 0; mt < 2; mt++) {
                uint32_t addr = base + a_off + mt*16*LDB + kk*32;
                ldsm_x4(ah[mt], addr);
                ldsm_x4(al[mt], addr + SZ_A);
            }
#pragma unroll
            for (int g = 0; g < 4; g++) {
                uint32_t addr = base + 2*SZ_A + b_off + g*16*LDB + kk*32;
                ldsm_x4(bb[g], addr);
            }
#pragma unroll
            for (int mt = 0; mt < 2; mt++)
#pragma unroll
                for (int nt = 0; nt < 8; nt++) {
                    const uint32_t* bp = &bb[nt >> 1][(nt & 1)*2];
                    mma16816h(acc[mt][nt], ah[mt], bp);
                    mma16816h(acc[mt][nt], al[mt], bp);
                }
        }
    }

#pragma unroll
    for (int mt = 0; mt < 2; mt++) {
        int r0 = m0 + wm*32 + mt*16 + (lane >> 2);
#pragma unroll
        for (int nt = 0; nt < 8; nt++) {
            int c0 = n0 + wn*64 + nt*8 + (lane & 3)*2;
            *(float2*)&Cm[(size_t)r0*C_ + c0] =
                make_float2(acc[mt][nt][0], acc[mt][nt][1]);
            *(float2*)&Cm[(size_t)(r0+8)*C_ + c0] =
                make_float2(acc[mt][nt][2], acc[mt][nt][3]);
        }
    }
}

__global__ void __launch_bounds__(512, 1) gemm_bf3b(GemmBatch gb)
{
    extern __shared__ char smem[];
    int z = blockIdx.z;
    gemm_core(gb.Ah[z], gb.Al[z], gb.Bh[z], gb.Cm[z], smem);
}

__global__ void __launch_bounds__(512, 1) gemm_bf3(
    const ushort_t* __restrict__ Ah, const ushort_t* __restrict__ Al,
    const ushort_t* __restrict__ Bh, float* __restrict__ Cm)
{
    extern __shared__ char smem[];
    gemm_core(Ah, Al, Bh, Cm, smem);
}

// ---------------- skinny GEMM + tanh (device body + wrappers) ----------------
template<int NS, bool FUSE>
__device__ __forceinline__ void skinny_body(
    const float* __restrict__ A, const float* __restrict__ W,
    float* __restrict__ out,
    const float* __restrict__ shift, const float* __restrict__ maax)
{
    __shared__ float As[32*68];
    __shared__ float Ws[32*NS];
    const int tid = threadIdx.x;
    const int m0  = blockIdx.x * 64;
    const int row = tid >> 2;
    const int cg  = tid & 3;

    float acc[NS/4];
#pragma unroll
    for (int i = 0; i < NS/4; i++) acc[i] = 0.f;

    for (int k0 = 0; k0 < C_; k0 += 32) {
#pragma unroll
        for (int e = 0; e < 2; e++) {
            int q  = tid + 256*e;
            int r  = q >> 3;
            int c4 = (q & 7) * 4;
            int m  = m0 + r;
            float4 val;
            if (FUSE) {
                float4 xv = *(const float4*)(A + (size_t)m*C_ + k0 + c4);
                int t = m & (T_-1);
                int b = m >> 11;
                float4 xp = (t > 0) ? *(const float4*)(A + (size_t)(m-1)*C_ + k0 + c4)
                                    : *(const float4*)(shift + (size_t)b*C_ + k0 + c4);
                float4 mx = *(const float4*)(maax + k0 + c4);
                val.x = xv.x + (xp.x - xv.x)*mx.x;
                val.y = xv.y + (xp.y - xv.y)*mx.y;
                val.z = xv.z + (xp.z - xv.z)*mx.z;
                val.w = xv.w + (xp.w - xv.w)*mx.w;
            } else {
                val = *(const float4*)(A + (size_t)m*C_ + k0 + c4);
            }
            As[(c4+0)*68 + r] = val.x;
            As[(c4+1)*68 + r] = val.y;
            As[(c4+2)*68 + r] = val.z;
            As[(c4+3)*68 + r] = val.w;
        }
        {
            const float4* src = (const float4*)(W + (size_t)k0*NS);
            for (int q = tid; q < 32*NS/4; q += 256)
                ((float4*)Ws)[q] = src[q];
        }
        __syncthreads();
#pragma unroll 8
        for (int k = 0; k < 32; k++) {
            float a = As[k*68 + row];
            const float* wrow = Ws + k*NS + cg*(NS/4);
#pragma unroll
            for (int j = 0; j < NS/16; j++) {
                float4 w4 = *(const float4*)(wrow + j*4);
                acc[j*4+0] = fmaf(a, w4.x, acc[j*4+0]);
                acc[j*4+1] = fmaf(a, w4.y, acc[j*4+1]);
                acc[j*4+2] = fmaf(a, w4.z, acc[j*4+2]);
                acc[j*4+3] = fmaf(a, w4.w, acc[j*4+3]);
            }
        }
        __syncthreads();
    }
    float* orow = out + (size_t)(m0+row)*NS + cg*(NS/4);
#pragma unroll
    for (int i = 0; i < NS/4; i++) orow[i] = tanhf(acc[i]);
}

__global__ void __launch_bounds__(256) skinny160_fuse(
    const float* A, const float* W, float* out,
    const float* shift, const float* maax)
{
    skinny_body<160, true>(A, W, out, shift, maax);
}

struct Skinny2 {
    const float* A[2];
    const float* W[2];
    float*       out[2];
};
__global__ void __launch_bounds__(256) skinny64_b(Skinny2 p)
{
    int z = blockIdx.y;
    skinny_body<64, false>(p.A[z], p.W[z], p.out[z], nullptr, nullptr);
}

// ---------------- 5-way mix apply (device body + wrappers) ----------------
// MODE 0: fp16 hi/lo split only.  MODE 1: fp32 only.  MODE 2: fp32 + split.
template<int MODE>
__device__ __forceinline__ void mix_body(
    const float* __restrict__ x, const float* __restrict__ shift,
    const float* __restrict__ tm, const float* __restrict__ w2,
    const float* __restrict__ maa,
    ushort_t* __restrict__ oh, ushort_t* __restrict__ ol,
    float* __restrict__ of, int f)
{
    __shared__ float tmf[32*32];
    __shared__ float w2f[32*64];
    int tid = threadIdx.x;
    int m0 = blockIdx.y * 32;
    int c0 = blockIdx.x * 64;
    {
        int r = tid >> 3, c4 = (tid & 7) * 4;
        *(float4*)&tmf[r*32 + c4] =
            *(const float4*)(tm + (size_t)(m0+r)*160 + f*32 + c4);
    }
#pragma unroll
    for (int e = 0; e < 2; e++) {
        int q = tid + 256*e;
        int d = q >> 4, c4 = (q & 15) * 4;
        *(float4*)&w2f[d*64 + c4] =
            *(const float4*)(w2 + (size_t)(f*32+d)*C_ + c0 + c4);
    }
    __syncthreads();
#pragma unroll
    for (int e = 0; e < 2; e++) {
        int p = tid + 256*e;
        int r  = p >> 4;
        int c4 = (p & 15) * 4;
        int m = m0 + r;
        int c = c0 + c4;
        float4 acc = make_float4(0.f,0.f,0.f,0.f);
#pragma unroll
        for (int d = 0; d < 32; d++) {
            float tv = tmf[r*32 + d];
            float4 w4 = *(const float4*)&w2f[d*64 + c4];
            acc.x = fmaf(tv, w4.x, acc.x);
            acc.y = fmaf(tv, w4.y, acc.y);
            acc.z = fmaf(tv, w4.z, acc.z);
            acc.w = fmaf(tv, w4.w, acc.w);
        }
        float4 xv = *(const float4*)(x + (size_t)m*C_ + c);
        int t = m & (T_-1), b = m >> 11;
        float4 xp = (t > 0) ? *(const float4*)(x + (size_t)(m-1)*C_ + c)
                            : *(const float4*)(shift + (size_t)b*C_ + c);
        float4 ma = *(const float4*)(maa + c);
        float4 o;
        o.x = xv.x + (xp.x - xv.x)*(ma.x + acc.x);
        o.y = xv.y + (xp.y - xv.y)*(ma.y + acc.y);
        o.z = xv.z + (xp.z - xv.z)*(ma.z + acc.z);
        o.w = xv.w + (xp.w - xv.w)*(ma.w + acc.w);
        size_t base = (size_t)m*C_ + c;
        if (MODE == 1 || MODE == 2)
            *(float4*)(of + base) = o;
        if (MODE == 0 || MODE == 2) {
            ushort4 h4, l4;
            split1(o.x, h4.x, l4.x);
            split1(o.y, h4.y, l4.y);
            split1(o.z, h4.z, l4.z);
            split1(o.w, h4.w, l4.w);
            *(ushort4*)(oh + base) = h4;
            *(ushort4*)(ol + base) = l4;
        }
    }
}

struct MixB {
    const float* maa[3];
    ushort_t*    oh[3];
    ushort_t*    ol[3];
};
__global__ void __launch_bounds__(256) mix_apply3(
    const float* x, const float* shift, const float* tm, const float* w2,
    MixB mb)
{
    int f = blockIdx.z;
    mix_body<0>(x, shift, tm, w2, mb.maa[f], mb.oh[f], mb.ol[f], nullptr, f);
}
template<int MODE>
__global__ void __launch_bounds__(256) mix_apply_f(
    const float* x, const float* shift, const float* tm, const float* w2,
    const float* maa, ushort_t* oh, ushort_t* ol, float* of, int f)
{
    mix_body<MODE>(x, shift, tm, w2, maa, oh, ol, of, f);
}

// ---------------- small-K GEMM (K=64) with fused epilogues ----------------
template<int MODE>
__global__ void __launch_bounds__(256) smallk_gemm(
    const float* __restrict__ A, const float* __restrict__ W,
    const float* __restrict__ td, float* __restrict__ out1)
{
    __shared__ float As[32*64];
    __shared__ float Ws[64*128];
    int tid = threadIdx.x;
    int m0 = blockIdx.y * 32, c0 = blockIdx.x * 128;
    {
        const float4* src = (const float4*)(A + (size_t)m0*64);
#pragma unroll
        for (int q = tid; q < 512; q += 256) ((float4*)As)[q] = src[q];
    }
#pragma unroll
    for (int e = 0; e < 8; e++) {
        int q = tid + 256*e;
        int kr = q >> 5, c4 = (q & 31) * 4;
        *(float4*)&Ws[kr*128 + c4] = *(const float4*)(W + (size_t)kr*C_ + c0 + c4);
    }
    __syncthreads();
    int ty = tid >> 4, tx = tid & 15;
    int r0 = ty * 2;
    float acc[2][8];
#pragma unroll
    for (int i = 0; i < 2; i++)
#pragma unroll
        for (int j = 0; j < 8; j++) acc[i][j] = 0.f;
#pragma unroll
    for (int k = 0; k < 64; k++) {
        float a0 = As[r0*64 + k];
        float a1 = As[(r0+1)*64 + k];
        float4 b0 = *(const float4*)&Ws[k*128 + tx*8];
        float4 b1 = *(const float4*)&Ws[k*128 + tx*8 + 4];
        float bv[8] = {b0.x,b0.y,b0.z,b0.w,b1.x,b1.y,b1.z,b1.w};
#pragma unroll
        for (int j = 0; j < 8; j++) {
            acc[0][j] = fmaf(a0, bv[j], acc[0][j]);
            acc[1][j] = fmaf(a1, bv[j], acc[1][j]);
        }
    }
#pragma unroll
    for (int rr = 0; rr < 2; rr++) {
        int m = m0 + r0 + rr;
        size_t base = (size_t)m*C_ + c0 + tx*8;
        if (MODE == 0) {
#pragma unroll
            for (int j = 0; j < 8; j++) {
                float w = td[c0 + tx*8 + j] + acc[rr][j];
                out1[base + j] = expf(-expf(w));
            }
        } else {
#pragma unroll
            for (int j = 0; j < 8; j++) out1[base + j] += acc[rr][j];
        }
    }
}

// ---------------- WKV scan (round-12 proven 64-thread version) ----------------
__global__ void __launch_bounds__(64) wkv_scan(
    const float* __restrict__ rp, const float* __restrict__ kp,
    const float* __restrict__ vp, const float* __restrict__ dp,
    const float* __restrict__ S0, float* __restrict__ yp,
    float* __restrict__ Sout)
{
    int bh = blockIdx.x;
    int j = threadIdx.x;
    int b = bh >> 5, h = bh & (H_-1);
    float S[64];
    const float* s0 = S0 + (size_t)bh*HS_*HS_ + j;
#pragma unroll
    for (int i = 0; i < 64; i++) S[i] = s0[(size_t)i*64];
    __shared__ float4 skd[64];
    size_t idx = (size_t)b*T_*C_ + (size_t)h*64 + j;
    float rr = rp[idx], kk = kp[idx], dd = dp[idx], vv = vp[idx];
    for (int t = 0; t < T_; t++) {
        float rn = 0.f, kn = 0.f, dn = 0.f, vn = 0.f;
        if (t + 1 < T_) {
            size_t nx = idx + C_;
            rn = rp[nx]; kn = kp[nx]; dn = dp[nx]; vn = vp[nx];
        }
        skd[j] = make_float4(rr, kk * (1.0f - dd), dd, 0.f);
        __syncthreads();
        float acc = 0.f;
#pragma unroll
        for (int i = 0; i < 64; i++) {
            float4 q = skd[i];
            acc  = fmaf(q.x, S[i], acc);
            S[i] = fmaf(q.z, S[i], q.y * vv);
        }
        yp[idx] = acc;
        __syncthreads();
        idx += C_;
        rr = rn; kk = kn; dd = dn; vv = vn;
    }
    float* so = Sout + (size_t)bh*HS_*HS_ + j;
#pragma unroll
    for (int i = 0; i < 64; i++) so[(size_t)i*64] = S[i];
}

// ---------------- fused add + LayerNorm, emits fp16 hi/lo split ----------------
__global__ void __launch_bounds__(256) ln_add_split(
    const float* __restrict__ a, const float* __restrict__ b,
    const float* __restrict__ lw, const float* __restrict__ lb,
    ushort_t* __restrict__ oh, ushort_t* __restrict__ ol)
{
    int m = blockIdx.x;
    int tid = threadIdx.x;
    const float* ar = a + (size_t)m*C_;
    const float* br = b + (size_t)m*C_;
    float vals[8];
    float s = 0.f, s2 = 0.f;
#pragma unroll
    for (int i = 0; i < 8; i++) {
        int c = tid + 256*i;
        float u = ar[c] + br[c];
        vals[i] = u; s += u; s2 = fmaf(u, u, s2);
    }
#pragma unroll
    for (int o = 16; o > 0; o >>= 1) {
        s  += __shfl_xor_sync(0xffffffffu, s,  o);
        s2 += __shfl_xor_sync(0xffffffffu, s2, o);
    }
    __shared__ float sa[8], sb2[8];
    if ((tid & 31) == 0) { sa[tid>>5] = s; sb2[tid>>5] = s2; }
    __syncthreads();
    s = 0.f; s2 = 0.f;
#pragma unroll
    for (int i = 0; i < 8; i++) { s += sa[i]; s2 += sb2[i]; }
    float mu  = s * (1.0f/C_);
    float var = s2 * (1.0f/C_) - mu*mu;
    float inv = rsqrtf(var + 1e-5f);
#pragma unroll
    for (int i = 0; i < 8; i++) {
        int c = tid + 256*i;
        float v = (vals[i] - mu)*inv*lw[c] + lb[c];
        ushort_t h, l;
        split1(v, h, l);
        oh[(size_t)m*C_ + c] = h;
        ol[(size_t)m*C_ + c] = l;
    }
}

__global__ void copy_xlast(const float* __restrict__ x, float* __restrict__ o)
{
    int i = blockIdx.x*256 + threadIdx.x;
    int b = i >> 11, c = i & (C_-1);
    o[i] = x[((size_t)b*T_ + (T_-1))*C_ + c];
}

// ---------------- launcher ----------------
extern "C" void kernel_launch(void* const* d_in, const int* in_sizes, int n_in,
                              void* d_out, int out_size)
{
    (void)in_sizes; (void)n_in;
    const float* x     = (const float*)d_in[0];
    const float* shift = (const float*)d_in[1];
    const float* wkv0  = (const float*)d_in[2];
    const float* maax  = (const float*)d_in[3];
    const float* maar  = (const float*)d_in[4];
    const float* maak  = (const float*)d_in[5];
    const float* maav  = (const float*)d_in[6];
    const float* maaw  = (const float*)d_in[7];
    const float* maav2 = (const float*)d_in[8];
    const float* w1    = (const float*)d_in[9];
    const float* w2    = (const float*)d_in[10];
    const float* tdec  = (const float*)d_in[11];
    const float* dw1   = (const float*)d_in[12];
    const float* dw2   = (const float*)d_in[13];
    const float* vw1   = (const float*)d_in[14];
    const float* vw2   = (const float*)d_in[15];
    const float* Wr    = (const float*)d_in[17];
    const float* Wk    = (const float*)d_in[18];
    const float* Wv    = (const float*)d_in[19];
    const float* Wo    = (const float*)d_in[20];
    const float* lnw   = (const float*)d_in[21];
    const float* lnb   = (const float*)d_in[22];
    float* out = (float*)d_out;

    float *tm,*xrf,*xkf,*xvf,*xw,*xv2,*rb,*kb,*vb,*v2b,*db,*lwv,*lv2,*yw;
    ushort_t *ah,*al,*wr,*wk,*wv,*wo;
    cudaGetSymbolAddress((void**)&tm,  g_tm);
    cudaGetSymbolAddress((void**)&xrf, g_xr);
    cudaGetSymbolAddress((void**)&xkf, g_xk);
    cudaGetSymbolAddress((void**)&xvf, g_xv);
    cudaGetSymbolAddress((void**)&xw,  g_xw);
    cudaGetSymbolAddress((void**)&xv2, g_xv2);
    cudaGetSymbolAddress((void**)&rb,  g_r);
    cudaGetSymbolAddress((void**)&kb,  g_k);
    cudaGetSymbolAddress((void**)&vb,  g_v);
    cudaGetSymbolAddress((void**)&v2b, g_v2);
    cudaGetSymbolAddress((void**)&db,  g_d);
    cudaGetSymbolAddress((void**)&lwv, g_lw);
    cudaGetSymbolAddress((void**)&lv2, g_lv2);
    cudaGetSymbolAddress((void**)&yw,  g_yw);
    cudaGetSymbolAddress((void**)&ah,  g_ah);
    cudaGetSymbolAddress((void**)&al,  g_al);
    cudaGetSymbolAddress((void**)&wr,  g_wr);
    cudaGetSymbolAddress((void**)&wk,  g_wk);
    cudaGetSymbolAddress((void**)&wv,  g_wv);
    cudaGetSymbolAddress((void**)&wo,  g_wo);

    ushort_t* xrh = (ushort_t*)xrf; ushort_t* xrl = xrh + (size_t)M_*C_;
    ushort_t* xkh = (ushort_t*)xkf; ushort_t* xkl = xkh + (size_t)M_*C_;
    ushort_t* xvh = (ushort_t*)xvf; ushort_t* xvl = xvh + (size_t)M_*C_;

    cudaFuncSetAttribute(gemm_bf3,  cudaFuncAttributeMaxDynamicSharedMemorySize, GEMM_SMEM);
    cudaFuncSetAttribute(gemm_bf3b, cudaFuncAttributeMaxDynamicSharedMemorySize, GEMM_SMEM);

    // 0) weight transpose + fp16 convert
    {
        dim3 gt(C_/32, C_/32);
        wsplit_t<<<gt,256>>>(Wr, wr);
        wsplit_t<<<gt,256>>>(Wk, wk);
        wsplit_t<<<gt,256>>>(Wv, wv);
        wsplit_t<<<gt,256>>>(Wo, wo);
    }

    // 1) LoRA-5 projection with fused token-shift mixing
    skinny160_fuse<<<M_/64, 256>>>(x, w1, tm, shift, maax);

    // 2) 5-way mix: z-batched MODE0 (r,k,v) + xw fp32 + xv2 both
    {
        dim3 g3(C_/64, M_/32, 3);
        MixB mb;
        mb.maa[0]=maar; mb.oh[0]=xrh; mb.ol[0]=xrl;
        mb.maa[1]=maak; mb.oh[1]=xkh; mb.ol[1]=xkl;
        mb.maa[2]=maav; mb.oh[2]=xvh; mb.ol[2]=xvl;
        mix_apply3<<<g3,256>>>(x, shift, tm, w2, mb);
        dim3 g(C_/64, M_/32);
        mix_apply_f<1><<<g,256>>>(x, shift, tm, w2, maaw,  nullptr, nullptr, xw, 3);
        mix_apply_f<2><<<g,256>>>(x, shift, tm, w2, maav2, ah, al, xv2, 4);
    }

    // 3) big projections via batched HMMA fp16x2 (z = r, k, v, v2)
    {
        GemmBatch gb;
        gb.Ah[0]=xrh; gb.Al[0]=xrl; gb.Bh[0]=wr; gb.Cm[0]=rb;
        gb.Ah[1]=xkh; gb.Al[1]=xkl; gb.Bh[1]=wk; gb.Cm[1]=kb;
        gb.Ah[2]=xvh; gb.Al[2]=xvl; gb.Bh[2]=wv; gb.Cm[2]=vb;
        gb.Ah[3]=ah;  gb.Al[3]=al;  gb.Bh[3]=wv; gb.Cm[3]=v2b;
        dim3 gb4(C_/256, M_/128, 4);
        gemm_bf3b<<<gb4,512,GEMM_SMEM>>>(gb);
    }

    // 4) decay / value2 LoRAs (batched skinny) + smallK epilogues
    {
        Skinny2 sp;
        sp.A[0]=xw;  sp.W[0]=dw1; sp.out[0]=lwv;
        sp.A[1]=xv2; sp.W[1]=vw1; sp.out[1]=lv2;
        dim3 gsk(M_/64, 2);
        skinny64_b<<<gsk,256>>>(sp);
        dim3 gs(C_/128, M_/32);
        smallk_gemm<0><<<gs,256>>>(lwv, dw2, tdec, db);      // d only
        smallk_gemm<1><<<gs,256>>>(lv2, vw2, nullptr, v2b);  // v2 += lora
    }

    // 5) WKV scan (64-thread proven), 6) LN, 7) output projection
    const size_t OFFS = (size_t)M_*C_;
    const size_t OFFX = OFFS + (size_t)B_*H_*HS_*HS_;
    bool full = (size_t)out_size >= OFFX + (size_t)B_*C_;
    float* Sout = full ? (out + OFFS) : tm;
    wkv_scan<<<B_*H_, 64>>>(rb, kb, vb, db, wkv0, yw, Sout);
    ln_add_split<<<M_, 256>>>(yw, v2b, lnw, lnb, ah, al);
    dim3 gg(C_/256, M_/128);
    gemm_bf3<<<gg,512,GEMM_SMEM>>>(ah, al, wo, out);
    if (full) copy_xlast<<<(B_*C_)/256, 256>>>(x, out + OFFX);
}

// round 15
// speedup vs baseline: 1.4457x; 1.0477x over previous
#include <cuda_runtime.h>
#include <cuda_fp16.h>
#include <math.h>
#include <stdint.h>

#define B_ 8
#define T_ 2048
#define C_ 2048
#define H_ 32
#define HS_ 64
#define M_ (B_*T_)   // 16384

typedef unsigned short ushort_t;

// ---------------- scratch (__device__ globals: allocation-free) ----------------
__device__ float g_tm [(size_t)M_*160];
__device__ float g_xr [(size_t)M_*C_];   // fp16 hi/lo split of xr
__device__ float g_xk [(size_t)M_*C_];   // fp16 hi/lo split of xk
__device__ float g_xv [(size_t)M_*C_];   // fp16 hi/lo split of xv
__device__ float g_xw [(size_t)M_*C_];   // fp16 hi/lo split of xw
__device__ float g_xv2[(size_t)M_*C_];   // (unused fp32; kept for layout)
__device__ float g_r  [(size_t)M_*C_];
__device__ float g_k  [(size_t)M_*C_];
__device__ float g_v  [(size_t)M_*C_];
__device__ float g_v2 [(size_t)M_*C_];
__device__ float g_d  [(size_t)M_*C_];
__device__ float g_lw [(size_t)M_*64];
__device__ float g_lv2[(size_t)M_*64];
__device__ float g_yw [(size_t)M_*C_];

// fp16 hi/lo split scratch (xv2 split, later yln split)
__device__ ushort_t g_ah[(size_t)M_*C_];
__device__ ushort_t g_al[(size_t)M_*C_];

// transposed fp16 weights: [N, K]
__device__ ushort_t g_wr[(size_t)C_*C_];
__device__ ushort_t g_wk[(size_t)C_*C_];
__device__ ushort_t g_wv[(size_t)C_*C_];
__device__ ushort_t g_wo[(size_t)C_*C_];

// ================= low-level helpers (base-target PTX only) =================
__device__ __forceinline__ uint32_t smem_u32(const void* p) {
    uint32_t a;
    asm("{ .reg .u64 t; cvta.to.shared.u64 t, %1; cvt.u32.u64 %0, t; }" : "=r"(a) : "l"(p));
    return a;
}
__device__ __forceinline__ void cp16(uint32_t dst, const void* src) {
    asm volatile("cp.async.cg.shared.global [%0], [%1], 16;" :: "r"(dst), "l"(src) : "memory");
}
#define CP_COMMIT() asm volatile("cp.async.commit_group;" ::: "memory")
#define CP_WAIT1()  asm volatile("cp.async.wait_group 1;"  ::: "memory")

__device__ __forceinline__ void ldsm_x4(uint32_t* r, uint32_t a) {
    asm volatile("ldmatrix.sync.aligned.m8n8.x4.shared.b16 {%0,%1,%2,%3}, [%4];"
        : "=r"(r[0]), "=r"(r[1]), "=r"(r[2]), "=r"(r[3]) : "r"(a));
}
__device__ __forceinline__ void mma16816h(float* c, const uint32_t* a, const uint32_t* b) {
    asm volatile("mma.sync.aligned.m16n8k16.row.col.f32.f16.f16.f32 "
        "{%0,%1,%2,%3}, {%4,%5,%6,%7}, {%8,%9}, {%0,%1,%2,%3};"
        : "+f"(c[0]), "+f"(c[1]), "+f"(c[2]), "+f"(c[3])
        : "r"(a[0]), "r"(a[1]), "r"(a[2]), "r"(a[3]), "r"(b[0]), "r"(b[1]));
}

__device__ __forceinline__ void split1(float v, ushort_t& h, ushort_t& l) {
    __half hb = __float2half_rn(v);
    h = __half_as_ushort(hb);
    l = __half_as_ushort(__float2half_rn(v - __half2float(hb)));
}
__device__ __forceinline__ float join1(ushort_t h, ushort_t l) {
    return __half2float(__ushort_as_half(h)) + __half2float(__ushort_as_half(l));
}

// ---------------- weight transpose + fp16 convert: T[n][k] = fp16(W[k][n]) ----------------
__global__ void __launch_bounds__(256) wsplit_t(
    const float* __restrict__ W, ushort_t* __restrict__ Th)
{
    __shared__ float ts[32][33];
    int n0 = blockIdx.x * 32, k0 = blockIdx.y * 32;
    int tx = threadIdx.x & 31, ty = threadIdx.x >> 5;
#pragma unroll
    for (int e = 0; e < 4; e++)
        ts[ty + 8*e][tx] = W[(size_t)(k0 + ty + 8*e)*C_ + n0 + tx];
    __syncthreads();
#pragma unroll
    for (int e = 0; e < 4; e++) {
        int n = ty + 8*e;
        Th[(size_t)(n0+n)*C_ + k0 + tx] =
            __half_as_ushort(__float2half_rn(ts[tx][n]));
    }
}

// ---------------- fp16x2 HMMA GEMM (round-12 proven) ----------------
#define LDB     80
#define SZ_A    (128*LDB)
#define SZ_B    (256*LDB)
#define STAGE_B (2*SZ_A + SZ_B)
#define NSTAGE  3
#define GEMM_SMEM (NSTAGE*STAGE_B)  // 122880

struct GemmBatch {
    const ushort_t* Ah[4];
    const ushort_t* Al[4];
    const ushort_t* Bh[4];
    float*          Cm[4];
};

__device__ __forceinline__ void gemm_load_stage(
    uint32_t sb, int s, const ushort_t* Ah, const ushort_t* Al,
    const ushort_t* Bh, int m0, int n0, int kt, int tid)
{
    int k0 = kt * 32;
    uint32_t base = sb + s*STAGE_B;
    {
        int row = tid >> 2, c = tid & 3;
        uint32_t d = base + row*LDB + c*16;
        size_t offA = (size_t)(m0 + row)*C_ + k0 + c*8;
        cp16(d,        Ah + offA);
        cp16(d + SZ_A, Al + offA);
    }
#pragma unroll
    for (int e = 0; e < 2; e++) {
        int q = tid + 512*e;
        int row = q >> 2, c = q & 3;
        uint32_t d = base + 2*SZ_A + row*LDB + c*16;
        size_t offB = (size_t)(n0 + row)*C_ + k0 + c*8;
        cp16(d, Bh + offB);
    }
    CP_COMMIT();
}

__device__ __forceinline__ void gemm_core(
    const ushort_t* __restrict__ Ah, const ushort_t* __restrict__ Al,
    const ushort_t* __restrict__ Bh, float* __restrict__ Cm, char* smem)
{
    uint32_t sb = smem_u32(smem);
    int tid = threadIdx.x, lane = tid & 31, w = tid >> 5;
    int wm = w & 3, wn = w >> 2;
    int m0 = blockIdx.y * 128, n0 = blockIdx.x * 256;

    float acc[2][8][4];
#pragma unroll
    for (int i = 0; i < 2; i++)
#pragma unroll
        for (int j = 0; j < 8; j++)
#pragma unroll
            for (int q = 0; q < 4; q++) acc[i][j][q] = 0.f;

    gemm_load_stage(sb, 0, Ah, Al, Bh, m0, n0, 0, tid);
    gemm_load_stage(sb, 1, Ah, Al, Bh, m0, n0, 1, tid);

    uint32_t a_off = (uint32_t)((wm*32 + (lane & 15))*LDB + (lane >> 4)*16);
    uint32_t b_off = (uint32_t)((wn*64 + (lane & 7) + ((lane >> 4) & 1)*8)*LDB
                                + ((lane >> 3) & 1)*16);

    for (int kt = 0; kt < C_/32; kt++) {
        int s = kt % NSTAGE;
        CP_WAIT1();
        __syncthreads();
        if (kt + 2 < C_/32)
            gemm_load_stage(sb, (kt+2) % NSTAGE, Ah, Al, Bh, m0, n0, kt+2, tid);

        uint32_t base = sb + s*STAGE_B;
#pragma unroll
        for (int kk = 0; kk < 2; kk++) {
            uint32_t ah[2][4], al[2][4], bb[4][4];
#pragma unroll
            for (int mt = 0; mt < 2; mt++) {
                uint32_t addr = base + a_off + mt*16*LDB + kk*32;
                ldsm_x4(ah[mt], addr);
                ldsm_x4(al[mt], addr + SZ_A);
            }
#pragma unroll
            for (int g = 0; g < 4; g++) {
                uint32_t addr = base + 2*SZ_A + b_off + g*16*LDB + kk*32;
                ldsm_x4(bb[g], addr);
            }
#pragma unroll
            for (int mt = 0; mt < 2; mt++)
#pragma unroll
                for (int nt = 0; nt < 8; nt++) {
                    const uint32_t* bp = &bb[nt >> 1][(nt & 1)*2];
                    mma16816h(acc[mt][nt], ah[mt], bp);
                    mma16816h(acc[mt][nt], al[mt], bp);
                }
        }
    }

#pragma unroll
    for (int mt = 0; mt < 2; mt++) {
        int r0 = m0 + wm*32 + mt*16 + (lane >> 2);
#pragma unroll
        for (int nt = 0; nt < 8; nt++) {
            int c0 = n0 + wn*64 + nt*8 + (lane & 3)*2;
            *(float2*)&Cm[(size_t)r0*C_ + c0] =
                make_float2(acc[mt][nt][0], acc[mt][nt][1]);
            *(float2*)&Cm[(size_t)(r0+8)*C_ + c0] =
                make_float2(acc[mt][nt][2], acc[mt][nt][3]);
        }
    }
}

__global__ void __launch_bounds__(512, 1) gemm_bf3b(GemmBatch gb)
{
    extern __shared__ char smem[];
    int z = blockIdx.z;
    gemm_core(gb.Ah[z], gb.Al[z], gb.Bh[z], gb.Cm[z], smem);
}

__global__ void __launch_bounds__(512, 1) gemm_bf3(
    const ushort_t* __restrict__ Ah, const ushort_t* __restrict__ Al,
    const ushort_t* __restrict__ Bh, float* __restrict__ Cm)
{
    extern __shared__ char smem[];
    gemm_core(Ah, Al, Bh, Cm, smem);
}

// ---------------- skinny GEMM + tanh ----------------
// SPLITIN=false: A fp32 (with optional FUSE token-shift). SPLITIN=true: A fp16 hi/lo.
template<int NS, bool FUSE, bool SPLITIN>
__device__ __forceinline__ void skinny_body(
    const float* __restrict__ A,
    const ushort_t* __restrict__ AH, const ushort_t* __restrict__ AL,
    const float* __restrict__ W, float* __restrict__ out,
    const float* __restrict__ shift, const float* __restrict__ maax)
{
    __shared__ float As[32*68];
    __shared__ float Ws[32*NS];
    const int tid = threadIdx.x;
    const int m0  = blockIdx.x * 64;
    const int row = tid >> 2;
    const int cg  = tid & 3;

    float acc[NS/4];
#pragma unroll
    for (int i = 0; i < NS/4; i++) acc[i] = 0.f;

    for (int k0 = 0; k0 < C_; k0 += 32) {
#pragma unroll
        for (int e = 0; e < 2; e++) {
            int q  = tid + 256*e;
            int r  = q >> 3;
            int c4 = (q & 7) * 4;
            int m  = m0 + r;
            float4 val;
            if (SPLITIN) {
                size_t off = (size_t)m*C_ + k0 + c4;
                ushort4 h4 = *(const ushort4*)(AH + off);
                ushort4 l4 = *(const ushort4*)(AL + off);
                val.x = join1(h4.x, l4.x);
                val.y = join1(h4.y, l4.y);
                val.z = join1(h4.z, l4.z);
                val.w = join1(h4.w, l4.w);
            } else if (FUSE) {
                float4 xv = *(const float4*)(A + (size_t)m*C_ + k0 + c4);
                int t = m & (T_-1);
                int b = m >> 11;
                float4 xp = (t > 0) ? *(const float4*)(A + (size_t)(m-1)*C_ + k0 + c4)
                                    : *(const float4*)(shift + (size_t)b*C_ + k0 + c4);
                float4 mx = *(const float4*)(maax + k0 + c4);
                val.x = xv.x + (xp.x - xv.x)*mx.x;
                val.y = xv.y + (xp.y - xv.y)*mx.y;
                val.z = xv.z + (xp.z - xv.z)*mx.z;
                val.w = xv.w + (xp.w - xv.w)*mx.w;
            } else {
                val = *(const float4*)(A + (size_t)m*C_ + k0 + c4);
            }
            As[(c4+0)*68 + r] = val.x;
            As[(c4+1)*68 + r] = val.y;
            As[(c4+2)*68 + r] = val.z;
            As[(c4+3)*68 + r] = val.w;
        }
        {
            const float4* src = (const float4*)(W + (size_t)k0*NS);
            for (int q = tid; q < 32*NS/4; q += 256)
                ((float4*)Ws)[q] = src[q];
        }
        __syncthreads();
#pragma unroll 8
        for (int k = 0; k < 32; k++) {
            float a = As[k*68 + row];
            const float* wrow = Ws + k*NS + cg*(NS/4);
#pragma unroll
            for (int j = 0; j < NS/16; j++) {
                float4 w4 = *(const float4*)(wrow + j*4);
                acc[j*4+0] = fmaf(a, w4.x, acc[j*4+0]);
                acc[j*4+1] = fmaf(a, w4.y, acc[j*4+1]);
                acc[j*4+2] = fmaf(a, w4.z, acc[j*4+2]);
                acc[j*4+3] = fmaf(a, w4.w, acc[j*4+3]);
            }
        }
        __syncthreads();
    }
    float* orow = out + (size_t)(m0+row)*NS + cg*(NS/4);
#pragma unroll
    for (int i = 0; i < NS/4; i++) orow[i] = tanhf(acc[i]);
}

__global__ void __launch_bounds__(256) skinny160_fuse(
    const float* A, const float* W, float* out,
    const float* shift, const float* maax)
{
    skinny_body<160, true, false>(A, nullptr, nullptr, W, out, shift, maax);
}

__global__ void __launch_bounds__(256) skinny64_split(
    const ushort_t* AH, const ushort_t* AL, const float* W, float* out)
{
    skinny_body<64, false, true>(nullptr, AH, AL, W, out, nullptr, nullptr);
}

// ---------------- 5-way mix apply, per-f, fp16 hi/lo split output ----------------
__global__ void __launch_bounds__(256) mix_apply_f(
    const float* __restrict__ x, const float* __restrict__ shift,
    const float* __restrict__ tm, const float* __restrict__ w2,
    const float* __restrict__ maa,
    ushort_t* __restrict__ oh, ushort_t* __restrict__ ol, int f)
{
    __shared__ float tmf[32*32];
    __shared__ float w2f[32*64];
    int tid = threadIdx.x;
    int m0 = blockIdx.y * 32;
    int c0 = blockIdx.x * 64;
    {
        int r = tid >> 3, c4 = (tid & 7) * 4;
        *(float4*)&tmf[r*32 + c4] =
            *(const float4*)(tm + (size_t)(m0+r)*160 + f*32 + c4);
    }
#pragma unroll
    for (int e = 0; e < 2; e++) {
        int q = tid + 256*e;
        int d = q >> 4, c4 = (q & 15) * 4;
        *(float4*)&w2f[d*64 + c4] =
            *(const float4*)(w2 + (size_t)(f*32+d)*C_ + c0 + c4);
    }
    __syncthreads();
#pragma unroll
    for (int e = 0; e < 2; e++) {
        int p = tid + 256*e;
        int r  = p >> 4;
        int c4 = (p & 15) * 4;
        int m = m0 + r;
        int c = c0 + c4;
        float4 acc = make_float4(0.f,0.f,0.f,0.f);
#pragma unroll
        for (int d = 0; d < 32; d++) {
            float tv = tmf[r*32 + d];
            float4 w4 = *(const float4*)&w2f[d*64 + c4];
            acc.x = fmaf(tv, w4.x, acc.x);
            acc.y = fmaf(tv, w4.y, acc.y);
            acc.z = fmaf(tv, w4.z, acc.z);
            acc.w = fmaf(tv, w4.w, acc.w);
        }
        float4 xv = *(const float4*)(x + (size_t)m*C_ + c);
        int t = m & (T_-1), b = m >> 11;
        float4 xp = (t > 0) ? *(const float4*)(x + (size_t)(m-1)*C_ + c)
                            : *(const float4*)(shift + (size_t)b*C_ + c);
        float4 ma = *(const float4*)(maa + c);
        float4 o;
        o.x = xv.x + (xp.x - xv.x)*(ma.x + acc.x);
        o.y = xv.y + (xp.y - xv.y)*(ma.y + acc.y);
        o.z = xv.z + (xp.z - xv.z)*(ma.z + acc.z);
        o.w = xv.w + (xp.w - xv.w)*(ma.w + acc.w);
        size_t base = (size_t)m*C_ + c;
        ushort4 h4, l4;
        split1(o.x, h4.x, l4.x);
        split1(o.y, h4.y, l4.y);
        split1(o.z, h4.z, l4.z);
        split1(o.w, h4.w, l4.w);
        *(ushort4*)(oh + base) = h4;
        *(ushort4*)(ol + base) = l4;
    }
}

// ---------------- small-K GEMM (K=64) with fused epilogues ----------------
template<int MODE>
__global__ void __launch_bounds__(256) smallk_gemm(
    const float* __restrict__ A, const float* __restrict__ W,
    const float* __restrict__ td, float* __restrict__ out1)
{
    __shared__ float As[32*64];
    __shared__ float Ws[64*128];
    int tid = threadIdx.x;
    int m0 = blockIdx.y * 32, c0 = blockIdx.x * 128;
    {
        const float4* src = (const float4*)(A + (size_t)m0*64);
#pragma unroll
        for (int q = tid; q < 512; q += 256) ((float4*)As)[q] = src[q];
    }
#pragma unroll
    for (int e = 0; e < 8; e++) {
        int q = tid + 256*e;
        int kr = q >> 5, c4 = (q & 31) * 4;
        *(float4*)&Ws[kr*128 + c4] = *(const float4*)(W + (size_t)kr*C_ + c0 + c4);
    }
    __syncthreads();
    int ty = tid >> 4, tx = tid & 15;
    int r0 = ty * 2;
    float acc[2][8];
#pragma unroll
    for (int i = 0; i < 2; i++)
#pragma unroll
        for (int j = 0; j < 8; j++) acc[i][j] = 0.f;
#pragma unroll
    for (int k = 0; k < 64; k++) {
        float a0 = As[r0*64 + k];
        float a1 = As[(r0+1)*64 + k];
        float4 b0 = *(const float4*)&Ws[k*128 + tx*8];
        float4 b1 = *(const float4*)&Ws[k*128 + tx*8 + 4];
        float bv[8] = {b0.x,b0.y,b0.z,b0.w,b1.x,b1.y,b1.z,b1.w};
#pragma unroll
        for (int j = 0; j < 8; j++) {
            acc[0][j] = fmaf(a0, bv[j], acc[0][j]);
            acc[1][j] = fmaf(a1, bv[j], acc[1][j]);
        }
    }
#pragma unroll
    for (int rr = 0; rr < 2; rr++) {
        int m = m0 + r0 + rr;
        size_t base = (size_t)m*C_ + c0 + tx*8;
        if (MODE == 0) {
#pragma unroll
            for (int j = 0; j < 8; j++) {
                float w = td[c0 + tx*8 + j] + acc[rr][j];
                out1[base + j] = expf(-expf(w));
            }
        } else {
#pragma unroll
            for (int j = 0; j < 8; j++) out1[base + j] += acc[rr][j];
        }
    }
}

// ---------------- WKV scan (round-12 proven 64-thread version) ----------------
__global__ void __launch_bounds__(64) wkv_scan(
    const float* __restrict__ rp, const float* __restrict__ kp,
    const float* __restrict__ vp, const float* __restrict__ dp,
    const float* __restrict__ S0, float* __restrict__ yp,
    float* __restrict__ Sout)
{
    int bh = blockIdx.x;
    int j = threadIdx.x;
    int b = bh >> 5, h = bh & (H_-1);
    float S[64];
    const float* s0 = S0 + (size_t)bh*HS_*HS_ + j;
#pragma unroll
    for (int i = 0; i < 64; i++) S[i] = s0[(size_t)i*64];
    __shared__ float4 skd[64];
    size_t idx = (size_t)b*T_*C_ + (size_t)h*64 + j;
    float rr = rp[idx], kk = kp[idx], dd = dp[idx], vv = vp[idx];
    for (int t = 0; t < T_; t++) {
        float rn = 0.f, kn = 0.f, dn = 0.f, vn = 0.f;
        if (t + 1 < T_) {
            size_t nx = idx + C_;
            rn = rp[nx]; kn = kp[nx]; dn = dp[nx]; vn = vp[nx];
        }
        skd[j] = make_float4(rr, kk * (1.0f - dd), dd, 0.f);
        __syncthreads();
        float acc = 0.f;
#pragma unroll
        for (int i = 0; i < 64; i++) {
            float4 q = skd[i];
            acc  = fmaf(q.x, S[i], acc);
            S[i] = fmaf(q.z, S[i], q.y * vv);
        }
        yp[idx] = acc;
        __syncthreads();
        idx += C_;
        rr = rn; kk = kn; dd = dn; vv = vn;
    }
    float* so = Sout + (size_t)bh*HS_*HS_ + j;
#pragma unroll
    for (int i = 0; i < 64; i++) so[(size_t)i*64] = S[i];
}

// ---------------- fused add + LayerNorm, emits fp16 hi/lo split ----------------
__global__ void __launch_bounds__(256) ln_add_split(
    const float* __restrict__ a, const float* __restrict__ b,
    const float* __restrict__ lw, const float* __restrict__ lb,
    ushort_t* __restrict__ oh, ushort_t* __restrict__ ol)
{
    int m = blockIdx.x;
    int tid = threadIdx.x;
    const float* ar = a + (size_t)m*C_;
    const float* br = b + (size_t)m*C_;
    float vals[8];
    float s = 0.f, s2 = 0.f;
#pragma unroll
    for (int i = 0; i < 8; i++) {
        int c = tid + 256*i;
        float u = ar[c] + br[c];
        vals[i] = u; s += u; s2 = fmaf(u, u, s2);
    }
#pragma unroll
    for (int o = 16; o > 0; o >>= 1) {
        s  += __shfl_xor_sync(0xffffffffu, s,  o);
        s2 += __shfl_xor_sync(0xffffffffu, s2, o);
    }
    __shared__ float sa[8], sb2[8];
    if ((tid & 31) == 0) { sa[tid>>5] = s; sb2[tid>>5] = s2; }
    __syncthreads();
    s = 0.f; s2 = 0.f;
#pragma unroll
    for (int i = 0; i < 8; i++) { s += sa[i]; s2 += sb2[i]; }
    float mu  = s * (1.0f/C_);
    float var = s2 * (1.0f/C_) - mu*mu;
    float inv = rsqrtf(var + 1e-5f);
#pragma unroll
    for (int i = 0; i < 8; i++) {
        int c = tid + 256*i;
        float v = (vals[i] - mu)*inv*lw[c] + lb[c];
        ushort_t h, l;
        split1(v, h, l);
        oh[(size_t)m*C_ + c] = h;
        ol[(size_t)m*C_ + c] = l;
    }
}

__global__ void copy_xlast(const float* __restrict__ x, float* __restrict__ o)
{
    int i = blockIdx.x*256 + threadIdx.x;
    int b = i >> 11, c = i & (C_-1);
    o[i] = x[((size_t)b*T_ + (T_-1))*C_ + c];
}

// ---------------- launcher ----------------
extern "C" void kernel_launch(void* const* d_in, const int* in_sizes, int n_in,
                              void* d_out, int out_size)
{
    (void)in_sizes; (void)n_in;
    const float* x     = (const float*)d_in[0];
    const float* shift = (const float*)d_in[1];
    const float* wkv0  = (const float*)d_in[2];
    const float* maax  = (const float*)d_in[3];
    const float* maar  = (const float*)d_in[4];
    const float* maak  = (const float*)d_in[5];
    const float* maav  = (const float*)d_in[6];
    const float* maaw  = (const float*)d_in[7];
    const float* maav2 = (const float*)d_in[8];
    const float* w1    = (const float*)d_in[9];
    const float* w2    = (const float*)d_in[10];
    const float* tdec  = (const float*)d_in[11];
    const float* dw1   = (const float*)d_in[12];
    const float* dw2   = (const float*)d_in[13];
    const float* vw1   = (const float*)d_in[14];
    const float* vw2   = (const float*)d_in[15];
    const float* Wr    = (const float*)d_in[17];
    const float* Wk    = (const float*)d_in[18];
    const float* Wv    = (const float*)d_in[19];
    const float* Wo    = (const float*)d_in[20];
    const float* lnw   = (const float*)d_in[21];
    const float* lnb   = (const float*)d_in[22];
    float* out = (float*)d_out;

    float *tm,*xrf,*xkf,*xvf,*xwf,*rb,*kb,*vb,*v2b,*db,*lwv,*lv2,*yw;
    ushort_t *ah,*al,*wr,*wk,*wv,*wo;
    cudaGetSymbolAddress((void**)&tm,  g_tm);
    cudaGetSymbolAddress((void**)&xrf, g_xr);
    cudaGetSymbolAddress((void**)&xkf, g_xk);
    cudaGetSymbolAddress((void**)&xvf, g_xv);
    cudaGetSymbolAddress((void**)&xwf, g_xw);
    cudaGetSymbolAddress((void**)&rb,  g_r);
    cudaGetSymbolAddress((void**)&kb,  g_k);
    cudaGetSymbolAddress((void**)&vb,  g_v);
    cudaGetSymbolAddress((void**)&v2b, g_v2);
    cudaGetSymbolAddress((void**)&db,  g_d);
    cudaGetSymbolAddress((void**)&lwv, g_lw);
    cudaGetSymbolAddress((void**)&lv2, g_lv2);
    cudaGetSymbolAddress((void**)&yw,  g_yw);
    cudaGetSymbolAddress((void**)&ah,  g_ah);
    cudaGetSymbolAddress((void**)&al,  g_al);
    cudaGetSymbolAddress((void**)&wr,  g_wr);
    cudaGetSymbolAddress((void**)&wk,  g_wk);
    cudaGetSymbolAddress((void**)&wv,  g_wv);
    cudaGetSymbolAddress((void**)&wo,  g_wo);

    // fp32 buffers reinterpreted as fp16 hi/lo pairs
    ushort_t* xrh = (ushort_t*)xrf; ushort_t* xrl = xrh + (size_t)M_*C_;
    ushort_t* xkh = (ushort_t*)xkf; ushort_t* xkl = xkh + (size_t)M_*C_;
    ushort_t* xvh = (ushort_t*)xvf; ushort_t* xvl = xvh + (size_t)M_*C_;
    ushort_t* xwh = (ushort_t*)xwf; ushort_t* xwl = xwh + (size_t)M_*C_;

    cudaFuncSetAttribute(gemm_bf3,  cudaFuncAttributeMaxDynamicSharedMemorySize, GEMM_SMEM);
    cudaFuncSetAttribute(gemm_bf3b, cudaFuncAttributeMaxDynamicSharedMemorySize, GEMM_SMEM);

    // 0) weight transpose + fp16 convert
    {
        dim3 gt(C_/32, C_/32);
        wsplit_t<<<gt,256>>>(Wr, wr);
        wsplit_t<<<gt,256>>>(Wk, wk);
        wsplit_t<<<gt,256>>>(Wv, wv);
        wsplit_t<<<gt,256>>>(Wo, wo);
    }

    // 1) LoRA-5 projection with fused token-shift mixing
    skinny160_fuse<<<M_/64, 256>>>(x, w1, tm, shift, maax);

    // 2) 5-way mix (all outputs fp16 hi/lo; 5 separate launches, r12 structure)
    {
        dim3 g(C_/64, M_/32);
        mix_apply_f<<<g,256>>>(x, shift, tm, w2, maar,  xrh, xrl, 0);
        mix_apply_f<<<g,256>>>(x, shift, tm, w2, maak,  xkh, xkl, 1);
        mix_apply_f<<<g,256>>>(x, shift, tm, w2, maav,  xvh, xvl, 2);
        mix_apply_f<<<g,256>>>(x, shift, tm, w2, maaw,  xwh, xwl, 3);
        mix_apply_f<<<g,256>>>(x, shift, tm, w2, maav2, ah,  al,  4);
    }

    // 3) big projections via batched HMMA fp16x2 (z = r, k, v, v2)
    {
        GemmBatch gb;
        gb.Ah[0]=xrh; gb.Al[0]=xrl; gb.Bh[0]=wr; gb.Cm[0]=rb;
        gb.Ah[1]=xkh; gb.Al[1]=xkl; gb.Bh[1]=wk; gb.Cm[1]=kb;
        gb.Ah[2]=xvh; gb.Al[2]=xvl; gb.Bh[2]=wv; gb.Cm[2]=vb;
        gb.Ah[3]=ah;  gb.Al[3]=al;  gb.Bh[3]=wv; gb.Cm[3]=v2b;
        dim3 gb4(C_/256, M_/128, 4);
        gemm_bf3b<<<gb4,512,GEMM_SMEM>>>(gb);
    }

    // 4) decay / value2 LoRAs (split-input skinny, 2 separate launches)
    skinny64_split<<<M_/64, 256>>>(xwh, xwl, dw1, lwv);
    skinny64_split<<<M_/64, 256>>>(ah,  al,  vw1, lv2);
    {
        dim3 gs(C_/128, M_/32);
        smallk_gemm<0><<<gs,256>>>(lwv, dw2, tdec, db);      // d only
        smallk_gemm<1><<<gs,256>>>(lv2, vw2, nullptr, v2b);  // v2 += lora
    }

    // 5) WKV scan, 6) LN, 7) output projection
    const size_t OFFS = (size_t)M_*C_;
    const size_t OFFX = OFFS + (size_t)B_*H_*HS_*HS_;
    bool full = (size_t)out_size >= OFFX + (size_t)B_*C_;
    float* Sout = full ? (out + OFFS) : tm;
    wkv_scan<<<B_*H_, 64>>>(rb, kb, vb, db, wkv0, yw, Sout);
    ln_add_split<<<M_, 256>>>(yw, v2b, lnw, lnb, ah, al);
    dim3 gg(C_/256, M_/128);
    gemm_bf3<<<gg,512,GEMM_SMEM>>>(ah, al, wo, out);
    if (full) copy_xlast<<<(B_*C_)/256, 256>>>(x, out + OFFX);
}

// round 16
// speedup vs baseline: 1.5612x; 1.0799x over previous
#include <cuda_runtime.h>
#include <cuda_fp16.h>
#include <math.h>
#include <stdint.h>

#define B_ 8
#define T_ 2048
#define C_ 2048
#define H_ 32
#define HS_ 64
#define M_ (B_*T_)   // 16384

typedef unsigned short ushort_t;

// ---------------- scratch (__device__ globals: allocation-free) ----------------
__device__ float g_tm [(size_t)M_*160];
__device__ float g_xr [(size_t)M_*C_];   // fp16 hi/lo split of xr
__device__ float g_xk [(size_t)M_*C_];   // fp16 hi/lo split of xk
__device__ float g_xv [(size_t)M_*C_];   // fp16 hi/lo split of xv
__device__ float g_xw [(size_t)M_*C_];   // fp16 hi/lo split of xw
__device__ float g_r  [(size_t)M_*C_];
__device__ float g_k  [(size_t)M_*C_];
__device__ float g_v  [(size_t)M_*C_];
__device__ float g_v2 [(size_t)M_*C_];
__device__ float g_d  [(size_t)M_*C_];
__device__ float g_lw [(size_t)M_*64];
__device__ float g_lv2[(size_t)M_*64];
__device__ float g_yw [(size_t)M_*C_];

// fp16 hi/lo split scratch (xxx split, then xv2 split, then yln split)
__device__ ushort_t g_ah[(size_t)M_*C_];
__device__ ushort_t g_al[(size_t)M_*C_];

// transposed fp16 weights: [N, K]
__device__ ushort_t g_wr[(size_t)C_*C_];
__device__ ushort_t g_wk[(size_t)C_*C_];
__device__ ushort_t g_wv[(size_t)C_*C_];
__device__ ushort_t g_wo[(size_t)C_*C_];
__device__ ushort_t g_w1t[(size_t)256*C_];   // w1 transposed, padded to 256 rows

// ================= low-level helpers (base-target PTX only) =================
__device__ __forceinline__ uint32_t smem_u32(const void* p) {
    uint32_t a;
    asm("{ .reg .u64 t; cvta.to.shared.u64 t, %1; cvt.u32.u64 %0, t; }" : "=r"(a) : "l"(p));
    return a;
}
__device__ __forceinline__ void cp16(uint32_t dst, const void* src) {
    asm volatile("cp.async.cg.shared.global [%0], [%1], 16;" :: "r"(dst), "l"(src) : "memory");
}
#define CP_COMMIT() asm volatile("cp.async.commit_group;" ::: "memory")
#define CP_WAIT1()  asm volatile("cp.async.wait_group 1;"  ::: "memory")

__device__ __forceinline__ void ldsm_x4(uint32_t* r, uint32_t a) {
    asm volatile("ldmatrix.sync.aligned.m8n8.x4.shared.b16 {%0,%1,%2,%3}, [%4];"
        : "=r"(r[0]), "=r"(r[1]), "=r"(r[2]), "=r"(r[3]) : "r"(a));
}
__device__ __forceinline__ void mma16816h(float* c, const uint32_t* a, const uint32_t* b) {
    asm volatile("mma.sync.aligned.m16n8k16.row.col.f32.f16.f16.f32 "
        "{%0,%1,%2,%3}, {%4,%5,%6,%7}, {%8,%9}, {%0,%1,%2,%3};"
        : "+f"(c[0]), "+f"(c[1]), "+f"(c[2]), "+f"(c[3])
        : "r"(a[0]), "r"(a[1]), "r"(a[2]), "r"(a[3]), "r"(b[0]), "r"(b[1]));
}

__device__ __forceinline__ void split1(float v, ushort_t& h, ushort_t& l) {
    __half hb = __float2half_rn(v);
    h = __half_as_ushort(hb);
    l = __half_as_ushort(__float2half_rn(v - __half2float(hb)));
}
__device__ __forceinline__ float join1(ushort_t h, ushort_t l) {
    return __half2float(__ushort_as_half(h)) + __half2float(__ushort_as_half(l));
}

// ---------------- weight transpose + fp16 convert: T[n][k] = fp16(W[k][n]) ----------------
__global__ void __launch_bounds__(256) wsplit_t(
    const float* __restrict__ W, ushort_t* __restrict__ Th)
{
    __shared__ float ts[32][33];
    int n0 = blockIdx.x * 32, k0 = blockIdx.y * 32;
    int tx = threadIdx.x & 31, ty = threadIdx.x >> 5;
#pragma unroll
    for (int e = 0; e < 4; e++)
        ts[ty + 8*e][tx] = W[(size_t)(k0 + ty + 8*e)*C_ + n0 + tx];
    __syncthreads();
#pragma unroll
    for (int e = 0; e < 4; e++) {
        int n = ty + 8*e;
        Th[(size_t)(n0+n)*C_ + k0 + tx] =
            __half_as_ushort(__float2half_rn(ts[tx][n]));
    }
}

// w1 [C,160] -> T[256,K] fp16, rows >=160 zero
__global__ void __launch_bounds__(256) wsplit160(
    const float* __restrict__ W1, ushort_t* __restrict__ Th)
{
    __shared__ float ts[32][33];
    int n0 = blockIdx.x * 32, k0 = blockIdx.y * 32;
    int tx = threadIdx.x & 31, ty = threadIdx.x >> 5;
#pragma unroll
    for (int e = 0; e < 4; e++) {
        int kk = ty + 8*e;
        int n  = n0 + tx;
        ts[kk][tx] = (n < 160) ? W1[(size_t)(k0 + kk)*160 + n] : 0.f;
    }
    __syncthreads();
#pragma unroll
    for (int e = 0; e < 4; e++) {
        int n = ty + 8*e;
        Th[(size_t)(n0+n)*C_ + k0 + tx] =
            __half_as_ushort(__float2half_rn(ts[tx][n]));
    }
}

// ---------------- xxx = x + dxprev*maax, emit fp16 hi/lo ----------------
__global__ void __launch_bounds__(256) xxx_split(
    const float* __restrict__ x, const float* __restrict__ shift,
    const float* __restrict__ maax,
    ushort_t* __restrict__ oh, ushort_t* __restrict__ ol)
{
    size_t i = ((size_t)blockIdx.x*256 + threadIdx.x) * 4;
    int m = (int)(i >> 11);           // i / C_
    int c = (int)(i & (C_-1));
    float4 xv = *(const float4*)(x + i);
    int t = m & (T_-1), b = m >> 11;
    float4 xp = (t > 0) ? *(const float4*)(x + i - C_)
                        : *(const float4*)(shift + (size_t)b*C_ + c);
    float4 mx = *(const float4*)(maax + c);
    float4 o;
    o.x = xv.x + (xp.x - xv.x)*mx.x;
    o.y = xv.y + (xp.y - xv.y)*mx.y;
    o.z = xv.z + (xp.z - xv.z)*mx.z;
    o.w = xv.w + (xp.w - xv.w)*mx.w;
    ushort4 h4, l4;
    split1(o.x, h4.x, l4.x); split1(o.y, h4.y, l4.y);
    split1(o.z, h4.z, l4.z); split1(o.w, h4.w, l4.w);
    *(ushort4*)(oh + i) = h4;
    *(ushort4*)(ol + i) = l4;
}

// ---------------- fp16x2 HMMA GEMM (round-12 proven core, + TANH variant) ----------------
#define LDB     80
#define SZ_A    (128*LDB)
#define SZ_B    (256*LDB)
#define STAGE_B (2*SZ_A + SZ_B)
#define NSTAGE  3
#define GEMM_SMEM (NSTAGE*STAGE_B)  // 122880

struct GemmBatch {
    const ushort_t* Ah[4];
    const ushort_t* Al[4];
    const ushort_t* Bh[4];
    float*          Cm[4];
};

__device__ __forceinline__ void gemm_load_stage(
    uint32_t sb, int s, const ushort_t* Ah, const ushort_t* Al,
    const ushort_t* Bh, int m0, int n0, int kt, int tid)
{
    int k0 = kt * 32;
    uint32_t base = sb + s*STAGE_B;
    {
        int row = tid >> 2, c = tid & 3;
        uint32_t d = base + row*LDB + c*16;
        size_t offA = (size_t)(m0 + row)*C_ + k0 + c*8;
        cp16(d,        Ah + offA);
        cp16(d + SZ_A, Al + offA);
    }
#pragma unroll
    for (int e = 0; e < 2; e++) {
        int q = tid + 512*e;
        int row = q >> 2, c = q & 3;
        uint32_t d = base + 2*SZ_A + row*LDB + c*16;
        size_t offB = (size_t)(n0 + row)*C_ + k0 + c*8;
        cp16(d, Bh + offB);
    }
    CP_COMMIT();
}

template<bool TANH>
__device__ __forceinline__ void gemm_core(
    const ushort_t* __restrict__ Ah, const ushort_t* __restrict__ Al,
    const ushort_t* __restrict__ Bh, float* __restrict__ Cm, char* smem)
{
    uint32_t sb = smem_u32(smem);
    int tid = threadIdx.x, lane = tid & 31, w = tid >> 5;
    int wm = w & 3, wn = w >> 2;
    int m0 = blockIdx.y * 128, n0 = blockIdx.x * 256;

    float acc[2][8][4];
#pragma unroll
    for (int i = 0; i < 2; i++)
#pragma unroll
        for (int j = 0; j < 8; j++)
#pragma unroll
            for (int q = 0; q < 4; q++) acc[i][j][q] = 0.f;

    gemm_load_stage(sb, 0, Ah, Al, Bh, m0, n0, 0, tid);
    gemm_load_stage(sb, 1, Ah, Al, Bh, m0, n0, 1, tid);

    uint32_t a_off = (uint32_t)((wm*32 + (lane & 15))*LDB + (lane >> 4)*16);
    uint32_t b_off = (uint32_t)((wn*64 + (lane & 7) + ((lane >> 4) & 1)*8)*LDB
                                + ((lane >> 3) & 1)*16);

    for (int kt = 0; kt < C_/32; kt++) {
        int s = kt % NSTAGE;
        CP_WAIT1();
        __syncthreads();
        if (kt + 2 < C_/32)
            gemm_load_stage(sb, (kt+2) % NSTAGE, Ah, Al, Bh, m0, n0, kt+2, tid);

        uint32_t base = sb + s*STAGE_B;
#pragma unroll
        for (int kk = 0; kk < 2; kk++) {
            uint32_t ah[2][4], al[2][4], bb[4][4];
#pragma unroll
            for (int mt = 0; mt < 2; mt++) {
                uint32_t addr = base + a_off + mt*16*LDB + kk*32;
                ldsm_x4(ah[mt], addr);
                ldsm_x4(al[mt], addr + SZ_A);
            }
#pragma unroll
            for (int g = 0; g < 4; g++) {
                uint32_t addr = base + 2*SZ_A + b_off + g*16*LDB + kk*32;
                ldsm_x4(bb[g], addr);
            }
#pragma unroll
            for (int mt = 0; mt < 2; mt++)
#pragma unroll
                for (int nt = 0; nt < 8; nt++) {
                    const uint32_t* bp = &bb[nt >> 1][(nt & 1)*2];
                    mma16816h(acc[mt][nt], ah[mt], bp);
                    mma16816h(acc[mt][nt], al[mt], bp);
                }
        }
    }

#pragma unroll
    for (int mt = 0; mt < 2; mt++) {
        int r0 = m0 + wm*32 + mt*16 + (lane >> 2);
#pragma unroll
        for (int nt = 0; nt < 8; nt++) {
            int c0 = n0 + wn*64 + nt*8 + (lane & 3)*2;
            if (TANH) {
                if (c0 < 160) {
                    *(float2*)&Cm[(size_t)r0*160 + c0] =
                        make_float2(tanhf(acc[mt][nt][0]), tanhf(acc[mt][nt][1]));
                    *(float2*)&Cm[(size_t)(r0+8)*160 + c0] =
                        make_float2(tanhf(acc[mt][nt][2]), tanhf(acc[mt][nt][3]));
                }
            } else {
                *(float2*)&Cm[(size_t)r0*C_ + c0] =
                    make_float2(acc[mt][nt][0], acc[mt][nt][1]);
                *(float2*)&Cm[(size_t)(r0+8)*C_ + c0] =
                    make_float2(acc[mt][nt][2], acc[mt][nt][3]);
            }
        }
    }
}

__global__ void __launch_bounds__(512, 1) gemm_bf3b(GemmBatch gb)
{
    extern __shared__ char smem[];
    int z = blockIdx.z;
    gemm_core<false>(gb.Ah[z], gb.Al[z], gb.Bh[z], gb.Cm[z], smem);
}

__global__ void __launch_bounds__(512, 1) gemm_bf3(
    const ushort_t* __restrict__ Ah, const ushort_t* __restrict__ Al,
    const ushort_t* __restrict__ Bh, float* __restrict__ Cm)
{
    extern __shared__ char smem[];
    gemm_core<false>(Ah, Al, Bh, Cm, smem);
}

__global__ void __launch_bounds__(512, 1) gemm_tanh(
    const ushort_t* __restrict__ Ah, const ushort_t* __restrict__ Al,
    const ushort_t* __restrict__ Bh, float* __restrict__ Cm)
{
    extern __shared__ char smem[];
    gemm_core<true>(Ah, Al, Bh, Cm, smem);
}

// ---------------- skinny GEMM + tanh (split input, K=64 LoRAs) ----------------
template<int NS>
__device__ __forceinline__ void skinny_body_split(
    const ushort_t* __restrict__ AH, const ushort_t* __restrict__ AL,
    const float* __restrict__ W, float* __restrict__ out)
{
    __shared__ float As[32*68];
    __shared__ float Ws[32*NS];
    const int tid = threadIdx.x;
    const int m0  = blockIdx.x * 64;
    const int row = tid >> 2;
    const int cg  = tid & 3;

    float acc[NS/4];
#pragma unroll
    for (int i = 0; i < NS/4; i++) acc[i] = 0.f;

    for (int k0 = 0; k0 < C_; k0 += 32) {
#pragma unroll
        for (int e = 0; e < 2; e++) {
            int q  = tid + 256*e;
            int r  = q >> 3;
            int c4 = (q & 7) * 4;
            int m  = m0 + r;
            size_t off = (size_t)m*C_ + k0 + c4;
            ushort4 h4 = *(const ushort4*)(AH + off);
            ushort4 l4 = *(const ushort4*)(AL + off);
            As[(c4+0)*68 + r] = join1(h4.x, l4.x);
            As[(c4+1)*68 + r] = join1(h4.y, l4.y);
            As[(c4+2)*68 + r] = join1(h4.z, l4.z);
            As[(c4+3)*68 + r] = join1(h4.w, l4.w);
        }
        {
            const float4* src = (const float4*)(W + (size_t)k0*NS);
            for (int q = tid; q < 32*NS/4; q += 256)
                ((float4*)Ws)[q] = src[q];
        }
        __syncthreads();
#pragma unroll 8
        for (int k = 0; k < 32; k++) {
            float a = As[k*68 + row];
            const float* wrow = Ws + k*NS + cg*(NS/4);
#pragma unroll
            for (int j = 0; j < NS/16; j++) {
                float4 w4 = *(const float4*)(wrow + j*4);
                acc[j*4+0] = fmaf(a, w4.x, acc[j*4+0]);
                acc[j*4+1] = fmaf(a, w4.y, acc[j*4+1]);
                acc[j*4+2] = fmaf(a, w4.z, acc[j*4+2]);
                acc[j*4+3] = fmaf(a, w4.w, acc[j*4+3]);
            }
        }
        __syncthreads();
    }
    float* orow = out + (size_t)(m0+row)*NS + cg*(NS/4);
#pragma unroll
    for (int i = 0; i < NS/4; i++) orow[i] = tanhf(acc[i]);
}

__global__ void __launch_bounds__(256) skinny64_split(
    const ushort_t* AH, const ushort_t* AL, const float* W, float* out)
{
    skinny_body_split<64>(AH, AL, W, out);
}

// ---------------- 5-way mix apply, per-f, fp16 hi/lo split output ----------------
__global__ void __launch_bounds__(256) mix_apply_f(
    const float* __restrict__ x, const float* __restrict__ shift,
    const float* __restrict__ tm, const float* __restrict__ w2,
    const float* __restrict__ maa,
    ushort_t* __restrict__ oh, ushort_t* __restrict__ ol, int f)
{
    __shared__ float tmf[32*32];
    __shared__ float w2f[32*64];
    int tid = threadIdx.x;
    int m0 = blockIdx.y * 32;
    int c0 = blockIdx.x * 64;
    {
        int r = tid >> 3, c4 = (tid & 7) * 4;
        *(float4*)&tmf[r*32 + c4] =
            *(const float4*)(tm + (size_t)(m0+r)*160 + f*32 + c4);
    }
#pragma unroll
    for (int e = 0; e < 2; e++) {
        int q = tid + 256*e;
        int d = q >> 4, c4 = (q & 15) * 4;
        *(float4*)&w2f[d*64 + c4] =
            *(const float4*)(w2 + (size_t)(f*32+d)*C_ + c0 + c4);
    }
    __syncthreads();
#pragma unroll
    for (int e = 0; e < 2; e++) {
        int p = tid + 256*e;
        int r  = p >> 4;
        int c4 = (p & 15) * 4;
        int m = m0 + r;
        int c = c0 + c4;
        float4 acc = make_float4(0.f,0.f,0.f,0.f);
#pragma unroll
        for (int d = 0; d < 32; d++) {
            float tv = tmf[r*32 + d];
            float4 w4 = *(const float4*)&w2f[d*64 + c4];
            acc.x = fmaf(tv, w4.x, acc.x);
            acc.y = fmaf(tv, w4.y, acc.y);
            acc.z = fmaf(tv, w4.z, acc.z);
            acc.w = fmaf(tv, w4.w, acc.w);
        }
        float4 xv = *(const float4*)(x + (size_t)m*C_ + c);
        int t = m & (T_-1), b = m >> 11;
        float4 xp = (t > 0) ? *(const float4*)(x + (size_t)(m-1)*C_ + c)
                            : *(const float4*)(shift + (size_t)b*C_ + c);
        float4 ma = *(const float4*)(maa + c);
        float4 o;
        o.x = xv.x + (xp.x - xv.x)*(ma.x + acc.x);
        o.y = xv.y + (xp.y - xv.y)*(ma.y + acc.y);
        o.z = xv.z + (xp.z - xv.z)*(ma.z + acc.z);
        o.w = xv.w + (xp.w - xv.w)*(ma.w + acc.w);
        size_t base = (size_t)m*C_ + c;
        ushort4 h4, l4;
        split1(o.x, h4.x, l4.x);
        split1(o.y, h4.y, l4.y);
        split1(o.z, h4.z, l4.z);
        split1(o.w, h4.w, l4.w);
        *(ushort4*)(oh + base) = h4;
        *(ushort4*)(ol + base) = l4;
    }
}

// ---------------- small-K GEMM (K=64) with fused epilogues ----------------
template<int MODE>
__global__ void __launch_bounds__(256) smallk_gemm(
    const float* __restrict__ A, const float* __restrict__ W,
    const float* __restrict__ td, float* __restrict__ out1)
{
    __shared__ float As[32*64];
    __shared__ float Ws[64*128];
    int tid = threadIdx.x;
    int m0 = blockIdx.y * 32, c0 = blockIdx.x * 128;
    {
        const float4* src = (const float4*)(A + (size_t)m0*64);
#pragma unroll
        for (int q = tid; q < 512; q += 256) ((float4*)As)[q] = src[q];
    }
#pragma unroll
    for (int e = 0; e < 8; e++) {
        int q = tid + 256*e;
        int kr = q >> 5, c4 = (q & 31) * 4;
        *(float4*)&Ws[kr*128 + c4] = *(const float4*)(W + (size_t)kr*C_ + c0 + c4);
    }
    __syncthreads();
    int ty = tid >> 4, tx = tid & 15;
    int r0 = ty * 2;
    float acc[2][8];
#pragma unroll
    for (int i = 0; i < 2; i++)
#pragma unroll
        for (int j = 0; j < 8; j++) acc[i][j] = 0.f;
#pragma unroll
    for (int k = 0; k < 64; k++) {
        float a0 = As[r0*64 + k];
        float a1 = As[(r0+1)*64 + k];
        float4 b0 = *(const float4*)&Ws[k*128 + tx*8];
        float4 b1 = *(const float4*)&Ws[k*128 + tx*8 + 4];
        float bv[8] = {b0.x,b0.y,b0.z,b0.w,b1.x,b1.y,b1.z,b1.w};
#pragma unroll
        for (int j = 0; j < 8; j++) {
            acc[0][j] = fmaf(a0, bv[j], acc[0][j]);
            acc[1][j] = fmaf(a1, bv[j], acc[1][j]);
        }
    }
#pragma unroll
    for (int rr = 0; rr < 2; rr++) {
        int m = m0 + r0 + rr;
        size_t base = (size_t)m*C_ + c0 + tx*8;
        if (MODE == 0) {
#pragma unroll
            for (int j = 0; j < 8; j++) {
                float w = td[c0 + tx*8 + j] + acc[rr][j];
                out1[base + j] = expf(-expf(w));
            }
        } else {
#pragma unroll
            for (int j = 0; j < 8; j++) out1[base + j] += acc[rr][j];
        }
    }
}

// ---------------- WKV scan (round-12 proven 64-thread version) ----------------
__global__ void __launch_bounds__(64) wkv_scan(
    const float* __restrict__ rp, const float* __restrict__ kp,
    const float* __restrict__ vp, const float* __restrict__ dp,
    const float* __restrict__ S0, float* __restrict__ yp,
    float* __restrict__ Sout)
{
    int bh = blockIdx.x;
    int j = threadIdx.x;
    int b = bh >> 5, h = bh & (H_-1);
    float S[64];
    const float* s0 = S0 + (size_t)bh*HS_*HS_ + j;
#pragma unroll
    for (int i = 0; i < 64; i++) S[i] = s0[(size_t)i*64];
    __shared__ float4 skd[64];
    size_t idx = (size_t)b*T_*C_ + (size_t)h*64 + j;
    float rr = rp[idx], kk = kp[idx], dd = dp[idx], vv = vp[idx];
    for (int t = 0; t < T_; t++) {
        float rn = 0.f, kn = 0.f, dn = 0.f, vn = 0.f;
        if (t + 1 < T_) {
            size_t nx = idx + C_;
            rn = rp[nx]; kn = kp[nx]; dn = dp[nx]; vn = vp[nx];
        }
        skd[j] = make_float4(rr, kk * (1.0f - dd), dd, 0.f);
        __syncthreads();
        float acc = 0.f;
#pragma unroll
        for (int i = 0; i < 64; i++) {
            float4 q = skd[i];
            acc  = fmaf(q.x, S[i], acc);
            S[i] = fmaf(q.z, S[i], q.y * vv);
        }
        yp[idx] = acc;
        __syncthreads();
        idx += C_;
        rr = rn; kk = kn; dd = dn; vv = vn;
    }
    float* so = Sout + (size_t)bh*HS_*HS_ + j;
#pragma unroll
    for (int i = 0; i < 64; i++) so[(size_t)i*64] = S[i];
}

// ---------------- fused add + LayerNorm, emits fp16 hi/lo split ----------------
__global__ void __launch_bounds__(256) ln_add_split(
    const float* __restrict__ a, const float* __restrict__ b,
    const float* __restrict__ lw, const float* __restrict__ lb,
    ushort_t* __restrict__ oh, ushort_t* __restrict__ ol)
{
    int m = blockIdx.x;
    int tid = threadIdx.x;
    const float* ar = a + (size_t)m*C_;
    const float* br = b + (size_t)m*C_;
    float vals[8];
    float s = 0.f, s2 = 0.f;
#pragma unroll
    for (int i = 0; i < 8; i++) {
        int c = tid + 256*i;
        float u = ar[c] + br[c];
        vals[i] = u; s += u; s2 = fmaf(u, u, s2);
    }
#pragma unroll
    for (int o = 16; o > 0; o >>= 1) {
        s  += __shfl_xor_sync(0xffffffffu, s,  o);
        s2 += __shfl_xor_sync(0xffffffffu, s2, o);
    }
    __shared__ float sa[8], sb2[8];
    if ((tid & 31) == 0) { sa[tid>>5] = s; sb2[tid>>5] = s2; }
    __syncthreads();
    s = 0.f; s2 = 0.f;
#pragma unroll
    for (int i = 0; i < 8; i++) { s += sa[i]; s2 += sb2[i]; }
    float mu  = s * (1.0f/C_);
    float var = s2 * (1.0f/C_) - mu*mu;
    float inv = rsqrtf(var + 1e-5f);
#pragma unroll
    for (int i = 0; i < 8; i++) {
        int c = tid + 256*i;
        float v = (vals[i] - mu)*inv*lw[c] + lb[c];
        ushort_t h, l;
        split1(v, h, l);
        oh[(size_t)m*C_ + c] = h;
        ol[(size_t)m*C_ + c] = l;
    }
}

__global__ void copy_xlast(const float* __restrict__ x, float* __restrict__ o)
{
    int i = blockIdx.x*256 + threadIdx.x;
    int b = i >> 11, c = i & (C_-1);
    o[i] = x[((size_t)b*T_ + (T_-1))*C_ + c];
}

// ---------------- launcher ----------------
extern "C" void kernel_launch(void* const* d_in, const int* in_sizes, int n_in,
                              void* d_out, int out_size)
{
    (void)in_sizes; (void)n_in;
    const float* x     = (const float*)d_in[0];
    const float* shift = (const float*)d_in[1];
    const float* wkv0  = (const float*)d_in[2];
    const float* maax  = (const float*)d_in[3];
    const float* maar  = (const float*)d_in[4];
    const float* maak  = (const float*)d_in[5];
    const float* maav  = (const float*)d_in[6];
    const float* maaw  = (const float*)d_in[7];
    const float* maav2 = (const float*)d_in[8];
    const float* w1    = (const float*)d_in[9];
    const float* w2    = (const float*)d_in[10];
    const float* tdec  = (const float*)d_in[11];
    const float* dw1   = (const float*)d_in[12];
    const float* dw2   = (const float*)d_in[13];
    const float* vw1   = (const float*)d_in[14];
    const float* vw2   = (const float*)d_in[15];
    const float* Wr    = (const float*)d_in[17];
    const float* Wk    = (const float*)d_in[18];
    const float* Wv    = (const float*)d_in[19];
    const float* Wo    = (const float*)d_in[20];
    const float* lnw   = (const float*)d_in[21];
    const float* lnb   = (const float*)d_in[22];
    float* out = (float*)d_out;

    float *tm,*xrf,*xkf,*xvf,*xwf,*rb,*kb,*vb,*v2b,*db,*lwv,*lv2,*yw;
    ushort_t *ah,*al,*wr,*wk,*wv,*wo,*w1t;
    cudaGetSymbolAddress((void**)&tm,  g_tm);
    cudaGetSymbolAddress((void**)&xrf, g_xr);
    cudaGetSymbolAddress((void**)&xkf, g_xk);
    cudaGetSymbolAddress((void**)&xvf, g_xv);
    cudaGetSymbolAddress((void**)&xwf, g_xw);
    cudaGetSymbolAddress((void**)&rb,  g_r);
    cudaGetSymbolAddress((void**)&kb,  g_k);
    cudaGetSymbolAddress((void**)&vb,  g_v);
    cudaGetSymbolAddress((void**)&v2b, g_v2);
    cudaGetSymbolAddress((void**)&db,  g_d);
    cudaGetSymbolAddress((void**)&lwv, g_lw);
    cudaGetSymbolAddress((void**)&lv2, g_lv2);
    cudaGetSymbolAddress((void**)&yw,  g_yw);
    cudaGetSymbolAddress((void**)&ah,  g_ah);
    cudaGetSymbolAddress((void**)&al,  g_al);
    cudaGetSymbolAddress((void**)&wr,  g_wr);
    cudaGetSymbolAddress((void**)&wk,  g_wk);
    cudaGetSymbolAddress((void**)&wv,  g_wv);
    cudaGetSymbolAddress((void**)&wo,  g_wo);
    cudaGetSymbolAddress((void**)&w1t, g_w1t);

    // fp32 buffers reinterpreted as fp16 hi/lo pairs
    ushort_t* xrh = (ushort_t*)xrf; ushort_t* xrl = xrh + (size_t)M_*C_;
    ushort_t* xkh = (ushort_t*)xkf; ushort_t* xkl = xkh + (size_t)M_*C_;
    ushort_t* xvh = (ushort_t*)xvf; ushort_t* xvl = xvh + (size_t)M_*C_;
    ushort_t* xwh = (ushort_t*)xwf; ushort_t* xwl = xwh + (size_t)M_*C_;

    cudaFuncSetAttribute(gemm_bf3,  cudaFuncAttributeMaxDynamicSharedMemorySize, GEMM_SMEM);
    cudaFuncSetAttribute(gemm_bf3b, cudaFuncAttributeMaxDynamicSharedMemorySize, GEMM_SMEM);
    cudaFuncSetAttribute(gemm_tanh, cudaFuncAttributeMaxDynamicSharedMemorySize, GEMM_SMEM);

    // 0) weight transposes + fp16 convert
    {
        dim3 gt(C_/32, C_/32);
        wsplit_t<<<gt,256>>>(Wr, wr);
        wsplit_t<<<gt,256>>>(Wk, wk);
        wsplit_t<<<gt,256>>>(Wv, wv);
        wsplit_t<<<gt,256>>>(Wo, wo);
        dim3 g1(256/32, C_/32);
        wsplit160<<<g1,256>>>(w1, w1t);
    }

    // 1) LoRA-5 projection via HMMA: xxx split, then tm = tanh(xxx @ w1)
    {
        const int NS = (int)(((size_t)M_*C_/4) / 256);
        xxx_split<<<NS,256>>>(x, shift, maax, ah, al);
        dim3 gT(1, M_/128);
        gemm_tanh<<<gT,512,GEMM_SMEM>>>(ah, al, w1t, tm);
    }

    // 2) 5-way mix (all outputs fp16 hi/lo; 5 separate launches)
    {
        dim3 g(C_/64, M_/32);
        mix_apply_f<<<g,256>>>(x, shift, tm, w2, maar,  xrh, xrl, 0);
        mix_apply_f<<<g,256>>>(x, shift, tm, w2, maak,  xkh, xkl, 1);
        mix_apply_f<<<g,256>>>(x, shift, tm, w2, maav,  xvh, xvl, 2);
        mix_apply_f<<<g,256>>>(x, shift, tm, w2, maaw,  xwh, xwl, 3);
        mix_apply_f<<<g,256>>>(x, shift, tm, w2, maav2, ah,  al,  4);
    }

    // 3) big projections via batched HMMA fp16x2 (z = r, k, v, v2)
    {
        GemmBatch gb;
        gb.Ah[0]=xrh; gb.Al[0]=xrl; gb.Bh[0]=wr; gb.Cm[0]=rb;
        gb.Ah[1]=xkh; gb.Al[1]=xkl; gb.Bh[1]=wk; gb.Cm[1]=kb;
        gb.Ah[2]=xvh; gb.Al[2]=xvl; gb.Bh[2]=wv; gb.Cm[2]=vb;
        gb.Ah[3]=ah;  gb.Al[3]=al;  gb.Bh[3]=wv; gb.Cm[3]=v2b;
        dim3 gb4(C_/256, M_/128, 4);
        gemm_bf3b<<<gb4,512,GEMM_SMEM>>>(gb);
    }

    // 4) decay / value2 LoRAs (split-input skinny) + smallK epilogues
    skinny64_split<<<M_/64, 256>>>(xwh, xwl, dw1, lwv);
    skinny64_split<<<M_/64, 256>>>(ah,  al,  vw1, lv2);
    {
        dim3 gs(C_/128, M_/32);
        smallk_gemm<0><<<gs,256>>>(lwv, dw2, tdec, db);      // d only
        smallk_gemm<1><<<gs,256>>>(lv2, vw2, nullptr, v2b);  // v2 += lora
    }

    // 5) WKV scan, 6) LN, 7) output projection
    const size_t OFFS = (size_t)M_*C_;
    const size_t OFFX = OFFS + (size_t)B_*H_*HS_*HS_;
    bool full = (size_t)out_size >= OFFX + (size_t)B_*C_;
    float* Sout = full ? (out + OFFS) : tm;
    wkv_scan<<<B_*H_, 64>>>(rb, kb, vb, db, wkv0, yw, Sout);
    ln_add_split<<<M_, 256>>>(yw, v2b, lnw, lnb, ah, al);
    dim3 gg(C_/256, M_/128);
    gemm_bf3<<<gg,512,GEMM_SMEM>>>(ah, al, wo, out);
    if (full) copy_xlast<<<(B_*C_)/256, 256>>>(x, out + OFFX);
}

// round 17
// speedup vs baseline: 1.5681x; 1.0044x over previous
#include <cuda_runtime.h>
#include <cuda_fp16.h>
#include <math.h>
#include <stdint.h>

#define B_ 8
#define T_ 2048
#define C_ 2048
#define H_ 32
#define HS_ 64
#define M_ (B_*T_)   // 16384

typedef unsigned short ushort_t;

// ---------------- scratch (__device__ globals: allocation-free) ----------------
__device__ float g_tm [(size_t)M_*160];
__device__ float g_xr [(size_t)M_*C_];   // fp16 hi/lo split of xr
__device__ float g_xk [(size_t)M_*C_];   // fp16 hi/lo split of xk
__device__ float g_xv [(size_t)M_*C_];   // fp16 hi/lo split of xv
__device__ float g_xw [(size_t)M_*C_];   // fp16 hi/lo split of xw
__device__ float g_r  [(size_t)M_*C_];   // fp16 r (half the buffer used)
__device__ float g_k  [(size_t)M_*C_];   // fp16 k
__device__ float g_v  [(size_t)M_*C_];   // fp16 v
__device__ float g_v2 [(size_t)M_*C_];
__device__ float g_d  [(size_t)M_*C_];
__device__ float g_lw [(size_t)M_*64];
__device__ float g_lv2[(size_t)M_*64];
__device__ float g_yw [(size_t)M_*C_];

// fp16 hi/lo split scratch (xxx split, then xv2 split, then yln split)
__device__ ushort_t g_ah[(size_t)M_*C_];
__device__ ushort_t g_al[(size_t)M_*C_];

// transposed fp16 weights: [N, K]
__device__ ushort_t g_wr[(size_t)C_*C_];
__device__ ushort_t g_wk[(size_t)C_*C_];
__device__ ushort_t g_wv[(size_t)C_*C_];
__device__ ushort_t g_wo[(size_t)C_*C_];
__device__ ushort_t g_w1t[(size_t)256*C_];   // w1 transposed, padded to 256 rows

// ================= low-level helpers (base-target PTX only) =================
__device__ __forceinline__ uint32_t smem_u32(const void* p) {
    uint32_t a;
    asm("{ .reg .u64 t; cvta.to.shared.u64 t, %1; cvt.u32.u64 %0, t; }" : "=r"(a) : "l"(p));
    return a;
}
__device__ __forceinline__ void cp16(uint32_t dst, const void* src) {
    asm volatile("cp.async.cg.shared.global [%0], [%1], 16;" :: "r"(dst), "l"(src) : "memory");
}
#define CP_COMMIT() asm volatile("cp.async.commit_group;" ::: "memory")
#define CP_WAIT1()  asm volatile("cp.async.wait_group 1;"  ::: "memory")

__device__ __forceinline__ void ldsm_x4(uint32_t* r, uint32_t a) {
    asm volatile("ldmatrix.sync.aligned.m8n8.x4.shared.b16 {%0,%1,%2,%3}, [%4];"
        : "=r"(r[0]), "=r"(r[1]), "=r"(r[2]), "=r"(r[3]) : "r"(a));
}
__device__ __forceinline__ void mma16816h(float* c, const uint32_t* a, const uint32_t* b) {
    asm volatile("mma.sync.aligned.m16n8k16.row.col.f32.f16.f16.f32 "
        "{%0,%1,%2,%3}, {%4,%5,%6,%7}, {%8,%9}, {%0,%1,%2,%3};"
        : "+f"(c[0]), "+f"(c[1]), "+f"(c[2]), "+f"(c[3])
        : "r"(a[0]), "r"(a[1]), "r"(a[2]), "r"(a[3]), "r"(b[0]), "r"(b[1]));
}

__device__ __forceinline__ void split1(float v, ushort_t& h, ushort_t& l) {
    __half hb = __float2half_rn(v);
    h = __half_as_ushort(hb);
    l = __half_as_ushort(__float2half_rn(v - __half2float(hb)));
}
__device__ __forceinline__ float join1(ushort_t h, ushort_t l) {
    return __half2float(__ushort_as_half(h)) + __half2float(__ushort_as_half(l));
}

// ---------------- weight transpose + fp16 convert: T[n][k] = fp16(W[k][n]) ----------------
__global__ void __launch_bounds__(256) wsplit_t(
    const float* __restrict__ W, ushort_t* __restrict__ Th)
{
    __shared__ float ts[32][33];
    int n0 = blockIdx.x * 32, k0 = blockIdx.y * 32;
    int tx = threadIdx.x & 31, ty = threadIdx.x >> 5;
#pragma unroll
    for (int e = 0; e < 4; e++)
        ts[ty + 8*e][tx] = W[(size_t)(k0 + ty + 8*e)*C_ + n0 + tx];
    __syncthreads();
#pragma unroll
    for (int e = 0; e < 4; e++) {
        int n = ty + 8*e;
        Th[(size_t)(n0+n)*C_ + k0 + tx] =
            __half_as_ushort(__float2half_rn(ts[tx][n]));
    }
}

// w1 [C,160] -> T[256,K] fp16, rows >=160 zero
__global__ void __launch_bounds__(256) wsplit160(
    const float* __restrict__ W1, ushort_t* __restrict__ Th)
{
    __shared__ float ts[32][33];
    int n0 = blockIdx.x * 32, k0 = blockIdx.y * 32;
    int tx = threadIdx.x & 31, ty = threadIdx.x >> 5;
#pragma unroll
    for (int e = 0; e < 4; e++) {
        int kk = ty + 8*e;
        int n  = n0 + tx;
        ts[kk][tx] = (n < 160) ? W1[(size_t)(k0 + kk)*160 + n] : 0.f;
    }
    __syncthreads();
#pragma unroll
    for (int e = 0; e < 4; e++) {
        int n = ty + 8*e;
        Th[(size_t)(n0+n)*C_ + k0 + tx] =
            __half_as_ushort(__float2half_rn(ts[tx][n]));
    }
}

// ---------------- xxx = x + dxprev*maax, emit fp16 hi/lo ----------------
__global__ void __launch_bounds__(256) xxx_split(
    const float* __restrict__ x, const float* __restrict__ shift,
    const float* __restrict__ maax,
    ushort_t* __restrict__ oh, ushort_t* __restrict__ ol)
{
    size_t i = ((size_t)blockIdx.x*256 + threadIdx.x) * 4;
    int m = (int)(i >> 11);
    int c = (int)(i & (C_-1));
    float4 xv = *(const float4*)(x + i);
    int t = m & (T_-1), b = m >> 11;
    float4 xp = (t > 0) ? *(const float4*)(x + i - C_)
                        : *(const float4*)(shift + (size_t)b*C_ + c);
    float4 mx = *(const float4*)(maax + c);
    float4 o;
    o.x = xv.x + (xp.x - xv.x)*mx.x;
    o.y = xv.y + (xp.y - xv.y)*mx.y;
    o.z = xv.z + (xp.z - xv.z)*mx.z;
    o.w = xv.w + (xp.w - xv.w)*mx.w;
    ushort4 h4, l4;
    split1(o.x, h4.x, l4.x); split1(o.y, h4.y, l4.y);
    split1(o.z, h4.z, l4.z); split1(o.w, h4.w, l4.w);
    *(ushort4*)(oh + i) = h4;
    *(ushort4*)(ol + i) = l4;
}

// ---------------- fp16x2 HMMA GEMM (proven core; epilogue fp32/fp16/tanh) ----------------
#define LDB     80
#define SZ_A    (128*LDB)
#define SZ_B    (256*LDB)
#define STAGE_B (2*SZ_A + SZ_B)
#define NSTAGE  3
#define GEMM_SMEM (NSTAGE*STAGE_B)  // 122880

struct GemmBatch {
    const ushort_t* Ah[4];
    const ushort_t* Al[4];
    const ushort_t* Bh[4];
    void*           Cm[4];
    int             half_out[4];
};

__device__ __forceinline__ void gemm_load_stage(
    uint32_t sb, int s, const ushort_t* Ah, const ushort_t* Al,
    const ushort_t* Bh, int m0, int n0, int kt, int tid)
{
    int k0 = kt * 32;
    uint32_t base = sb + s*STAGE_B;
    {
        int row = tid >> 2, c = tid & 3;
        uint32_t d = base + row*LDB + c*16;
        size_t offA = (size_t)(m0 + row)*C_ + k0 + c*8;
        cp16(d,        Ah + offA);
        cp16(d + SZ_A, Al + offA);
    }
#pragma unroll
    for (int e = 0; e < 2; e++) {
        int q = tid + 512*e;
        int row = q >> 2, c = q & 3;
        uint32_t d = base + 2*SZ_A + row*LDB + c*16;
        size_t offB = (size_t)(n0 + row)*C_ + k0 + c*8;
        cp16(d, Bh + offB);
    }
    CP_COMMIT();
}

// EPI: 0 = fp32 store, 1 = runtime fp16/fp32 select, 2 = tanh stride-160
template<int EPI>
__device__ __forceinline__ void gemm_core(
    const ushort_t* __restrict__ Ah, const ushort_t* __restrict__ Al,
    const ushort_t* __restrict__ Bh, void* __restrict__ CmV,
    int half_out, char* smem)
{
    uint32_t sb = smem_u32(smem);
    int tid = threadIdx.x, lane = tid & 31, w = tid >> 5;
    int wm = w & 3, wn = w >> 2;
    int m0 = blockIdx.y * 128, n0 = blockIdx.x * 256;

    float acc[2][8][4];
#pragma unroll
    for (int i = 0; i < 2; i++)
#pragma unroll
        for (int j = 0; j < 8; j++)
#pragma unroll
            for (int q = 0; q < 4; q++) acc[i][j][q] = 0.f;

    gemm_load_stage(sb, 0, Ah, Al, Bh, m0, n0, 0, tid);
    gemm_load_stage(sb, 1, Ah, Al, Bh, m0, n0, 1, tid);

    uint32_t a_off = (uint32_t)((wm*32 + (lane & 15))*LDB + (lane >> 4)*16);
    uint32_t b_off = (uint32_t)((wn*64 + (lane & 7) + ((lane >> 4) & 1)*8)*LDB
                                + ((lane >> 3) & 1)*16);

    for (int kt = 0; kt < C_/32; kt++) {
        int s = kt % NSTAGE;
        CP_WAIT1();
        __syncthreads();
        if (kt + 2 < C_/32)
            gemm_load_stage(sb, (kt+2) % NSTAGE, Ah, Al, Bh, m0, n0, kt+2, tid);

        uint32_t base = sb + s*STAGE_B;
#pragma unroll
        for (int kk = 0; kk < 2; kk++) {
            uint32_t ah[2][4], al[2][4], bb[4][4];
#pragma unroll
            for (int mt = 0; mt < 2; mt++) {
                uint32_t addr = base + a_off + mt*16*LDB + kk*32;
                ldsm_x4(ah[mt], addr);
                ldsm_x4(al[mt], addr + SZ_A);
            }
#pragma unroll
            for (int g = 0; g < 4; g++) {
                uint32_t addr = base + 2*SZ_A + b_off + g*16*LDB + kk*32;
                ldsm_x4(bb[g], addr);
            }
#pragma unroll
            for (int mt = 0; mt < 2; mt++)
#pragma unroll
                for (int nt = 0; nt < 8; nt++) {
                    const uint32_t* bp = &bb[nt >> 1][(nt & 1)*2];
                    mma16816h(acc[mt][nt], ah[mt], bp);
                    mma16816h(acc[mt][nt], al[mt], bp);
                }
        }
    }

    float* Cm = (float*)CmV;
    ushort_t* Ch = (ushort_t*)CmV;
#pragma unroll
    for (int mt = 0; mt < 2; mt++) {
        int r0 = m0 + wm*32 + mt*16 + (lane >> 2);
#pragma unroll
        for (int nt = 0; nt < 8; nt++) {
            int c0 = n0 + wn*64 + nt*8 + (lane & 3)*2;
            if (EPI == 2) {
                if (c0 < 160) {
                    *(float2*)&Cm[(size_t)r0*160 + c0] =
                        make_float2(tanhf(acc[mt][nt][0]), tanhf(acc[mt][nt][1]));
                    *(float2*)&Cm[(size_t)(r0+8)*160 + c0] =
                        make_float2(tanhf(acc[mt][nt][2]), tanhf(acc[mt][nt][3]));
                }
            } else if (EPI == 1 && half_out) {
                __half2 p0 = __floats2half2_rn(acc[mt][nt][0], acc[mt][nt][1]);
                __half2 p1 = __floats2half2_rn(acc[mt][nt][2], acc[mt][nt][3]);
                *(__half2*)&Ch[(size_t)r0*C_ + c0]     = p0;
                *(__half2*)&Ch[(size_t)(r0+8)*C_ + c0] = p1;
            } else {
                *(float2*)&Cm[(size_t)r0*C_ + c0] =
                    make_float2(acc[mt][nt][0], acc[mt][nt][1]);
                *(float2*)&Cm[(size_t)(r0+8)*C_ + c0] =
                    make_float2(acc[mt][nt][2], acc[mt][nt][3]);
            }
        }
    }
}

__global__ void __launch_bounds__(512, 1) gemm_bf3b(GemmBatch gb)
{
    extern __shared__ char smem[];
    int z = blockIdx.z;
    gemm_core<1>(gb.Ah[z], gb.Al[z], gb.Bh[z], gb.Cm[z], gb.half_out[z], smem);
}

__global__ void __launch_bounds__(512, 1) gemm_bf3(
    const ushort_t* __restrict__ Ah, const ushort_t* __restrict__ Al,
    const ushort_t* __restrict__ Bh, float* __restrict__ Cm)
{
    extern __shared__ char smem[];
    gemm_core<0>(Ah, Al, Bh, Cm, 0, smem);
}

__global__ void __launch_bounds__(512, 1) gemm_tanh(
    const ushort_t* __restrict__ Ah, const ushort_t* __restrict__ Al,
    const ushort_t* __restrict__ Bh, float* __restrict__ Cm)
{
    extern __shared__ char smem[];
    gemm_core<2>(Ah, Al, Bh, Cm, 0, smem);
}

// ---------------- skinny GEMM + tanh (split input, K=64 LoRAs) ----------------
template<int NS>
__device__ __forceinline__ void skinny_body_split(
    const ushort_t* __restrict__ AH, const ushort_t* __restrict__ AL,
    const float* __restrict__ W, float* __restrict__ out)
{
    __shared__ float As[32*68];
    __shared__ float Ws[32*NS];
    const int tid = threadIdx.x;
    const int m0  = blockIdx.x * 64;
    const int row = tid >> 2;
    const int cg  = tid & 3;

    float acc[NS/4];
#pragma unroll
    for (int i = 0; i < NS/4; i++) acc[i] = 0.f;

    for (int k0 = 0; k0 < C_; k0 += 32) {
#pragma unroll
        for (int e = 0; e < 2; e++) {
            int q  = tid + 256*e;
            int r  = q >> 3;
            int c4 = (q & 7) * 4;
            int m  = m0 + r;
            size_t off = (size_t)m*C_ + k0 + c4;
            ushort4 h4 = *(const ushort4*)(AH + off);
            ushort4 l4 = *(const ushort4*)(AL + off);
            As[(c4+0)*68 + r] = join1(h4.x, l4.x);
            As[(c4+1)*68 + r] = join1(h4.y, l4.y);
            As[(c4+2)*68 + r] = join1(h4.z, l4.z);
            As[(c4+3)*68 + r] = join1(h4.w, l4.w);
        }
        {
            const float4* src = (const float4*)(W + (size_t)k0*NS);
            for (int q = tid; q < 32*NS/4; q += 256)
                ((float4*)Ws)[q] = src[q];
        }
        __syncthreads();
#pragma unroll 8
        for (int k = 0; k < 32; k++) {
            float a = As[k*68 + row];
            const float* wrow = Ws + k*NS + cg*(NS/4);
#pragma unroll
            for (int j = 0; j < NS/16; j++) {
                float4 w4 = *(const float4*)(wrow + j*4);
                acc[j*4+0] = fmaf(a, w4.x, acc[j*4+0]);
                acc[j*4+1] = fmaf(a, w4.y, acc[j*4+1]);
                acc[j*4+2] = fmaf(a, w4.z, acc[j*4+2]);
                acc[j*4+3] = fmaf(a, w4.w, acc[j*4+3]);
            }
        }
        __syncthreads();
    }
    float* orow = out + (size_t)(m0+row)*NS + cg*(NS/4);
#pragma unroll
    for (int i = 0; i < NS/4; i++) orow[i] = tanhf(acc[i]);
}

__global__ void __launch_bounds__(256) skinny64_split(
    const ushort_t* AH, const ushort_t* AL, const float* W, float* out)
{
    skinny_body_split<64>(AH, AL, W, out);
}

// ---------------- 5-way mix apply, per-f, fp16 hi/lo split output ----------------
__global__ void __launch_bounds__(256) mix_apply_f(
    const float* __restrict__ x, const float* __restrict__ shift,
    const float* __restrict__ tm, const float* __restrict__ w2,
    const float* __restrict__ maa,
    ushort_t* __restrict__ oh, ushort_t* __restrict__ ol, int f)
{
    __shared__ float tmf[32*32];
    __shared__ float w2f[32*64];
    int tid = threadIdx.x;
    int m0 = blockIdx.y * 32;
    int c0 = blockIdx.x * 64;
    {
        int r = tid >> 3, c4 = (tid & 7) * 4;
        *(float4*)&tmf[r*32 + c4] =
            *(const float4*)(tm + (size_t)(m0+r)*160 + f*32 + c4);
    }
#pragma unroll
    for (int e = 0; e < 2; e++) {
        int q = tid + 256*e;
        int d = q >> 4, c4 = (q & 15) * 4;
        *(float4*)&w2f[d*64 + c4] =
            *(const float4*)(w2 + (size_t)(f*32+d)*C_ + c0 + c4);
    }
    __syncthreads();
#pragma unroll
    for (int e = 0; e < 2; e++) {
        int p = tid + 256*e;
        int r  = p >> 4;
        int c4 = (p & 15) * 4;
        int m = m0 + r;
        int c = c0 + c4;
        float4 acc = make_float4(0.f,0.f,0.f,0.f);
#pragma unroll
        for (int d = 0; d < 32; d++) {
            float tv = tmf[r*32 + d];
            float4 w4 = *(const float4*)&w2f[d*64 + c4];
            acc.x = fmaf(tv, w4.x, acc.x);
            acc.y = fmaf(tv, w4.y, acc.y);
            acc.z = fmaf(tv, w4.z, acc.z);
            acc.w = fmaf(tv, w4.w, acc.w);
        }
        float4 xv = *(const float4*)(x + (size_t)m*C_ + c);
        int t = m & (T_-1), b = m >> 11;
        float4 xp = (t > 0) ? *(const float4*)(x + (size_t)(m-1)*C_ + c)
                            : *(const float4*)(shift + (size_t)b*C_ + c);
        float4 ma = *(const float4*)(maa + c);
        float4 o;
        o.x = xv.x + (xp.x - xv.x)*(ma.x + acc.x);
        o.y = xv.y + (xp.y - xv.y)*(ma.y + acc.y);
        o.z = xv.z + (xp.z - xv.z)*(ma.z + acc.z);
        o.w = xv.w + (xp.w - xv.w)*(ma.w + acc.w);
        size_t base = (size_t)m*C_ + c;
        ushort4 h4, l4;
        split1(o.x, h4.x, l4.x);
        split1(o.y, h4.y, l4.y);
        split1(o.z, h4.z, l4.z);
        split1(o.w, h4.w, l4.w);
        *(ushort4*)(oh + base) = h4;
        *(ushort4*)(ol + base) = l4;
    }
}

// ---------------- small-K GEMM (K=64) with fused epilogues ----------------
template<int MODE>
__global__ void __launch_bounds__(256) smallk_gemm(
    const float* __restrict__ A, const float* __restrict__ W,
    const float* __restrict__ td, float* __restrict__ out1)
{
    __shared__ float As[32*64];
    __shared__ float Ws[64*128];
    int tid = threadIdx.x;
    int m0 = blockIdx.y * 32, c0 = blockIdx.x * 128;
    {
        const float4* src = (const float4*)(A + (size_t)m0*64);
#pragma unroll
        for (int q = tid; q < 512; q += 256) ((float4*)As)[q] = src[q];
    }
#pragma unroll
    for (int e = 0; e < 8; e++) {
        int q = tid + 256*e;
        int kr = q >> 5, c4 = (q & 31) * 4;
        *(float4*)&Ws[kr*128 + c4] = *(const float4*)(W + (size_t)kr*C_ + c0 + c4);
    }
    __syncthreads();
    int ty = tid >> 4, tx = tid & 15;
    int r0 = ty * 2;
    float acc[2][8];
#pragma unroll
    for (int i = 0; i < 2; i++)
#pragma unroll
        for (int j = 0; j < 8; j++) acc[i][j] = 0.f;
#pragma unroll
    for (int k = 0; k < 64; k++) {
        float a0 = As[r0*64 + k];
        float a1 = As[(r0+1)*64 + k];
        float4 b0 = *(const float4*)&Ws[k*128 + tx*8];
        float4 b1 = *(const float4*)&Ws[k*128 + tx*8 + 4];
        float bv[8] = {b0.x,b0.y,b0.z,b0.w,b1.x,b1.y,b1.z,b1.w};
#pragma unroll
        for (int j = 0; j < 8; j++) {
            acc[0][j] = fmaf(a0, bv[j], acc[0][j]);
            acc[1][j] = fmaf(a1, bv[j], acc[1][j]);
        }
    }
#pragma unroll
    for (int rr = 0; rr < 2; rr++) {
        int m = m0 + r0 + rr;
        size_t base = (size_t)m*C_ + c0 + tx*8;
        if (MODE == 0) {
#pragma unroll
            for (int j = 0; j < 8; j++) {
                float w = td[c0 + tx*8 + j] + acc[rr][j];
                out1[base + j] = expf(-expf(w));
            }
        } else {
#pragma unroll
            for (int j = 0; j < 8; j++) out1[base + j] += acc[rr][j];
        }
    }
}

// ---------------- WKV scan (fp16 r/k/v, fp32 d) ----------------
__global__ void __launch_bounds__(64) wkv_scan(
    const __half* __restrict__ rp, const __half* __restrict__ kp,
    const __half* __restrict__ vp, const float* __restrict__ dp,
    const float* __restrict__ S0, float* __restrict__ yp,
    float* __restrict__ Sout)
{
    int bh = blockIdx.x;
    int j = threadIdx.x;
    int b = bh >> 5, h = bh & (H_-1);
    float S[64];
    const float* s0 = S0 + (size_t)bh*HS_*HS_ + j;
#pragma unroll
    for (int i = 0; i < 64; i++) S[i] = s0[(size_t)i*64];
    __shared__ float4 skd[64];
    size_t idx = (size_t)b*T_*C_ + (size_t)h*64 + j;
    float rr = __half2float(rp[idx]), kk = __half2float(kp[idx]);
    float dd = dp[idx], vv = __half2float(vp[idx]);
    for (int t = 0; t < T_; t++) {
        float rn = 0.f, kn = 0.f, dn = 0.f, vn = 0.f;
        if (t + 1 < T_) {
            size_t nx = idx + C_;
            rn = __half2float(rp[nx]); kn = __half2float(kp[nx]);
            dn = dp[nx]; vn = __half2float(vp[nx]);
        }
        skd[j] = make_float4(rr, kk * (1.0f - dd), dd, 0.f);
        __syncthreads();
        float acc = 0.f;
#pragma unroll
        for (int i = 0; i < 64; i++) {
            float4 q = skd[i];
            acc  = fmaf(q.x, S[i], acc);
            S[i] = fmaf(q.z, S[i], q.y * vv);
        }
        yp[idx] = acc;
        __syncthreads();
        idx += C_;
        rr = rn; kk = kn; dd = dn; vv = vn;
    }
    float* so = Sout + (size_t)bh*HS_*HS_ + j;
#pragma unroll
    for (int i = 0; i < 64; i++) so[(size_t)i*64] = S[i];
}

// ---------------- fused add + LayerNorm, emits fp16 hi/lo split ----------------
__global__ void __launch_bounds__(256) ln_add_split(
    const float* __restrict__ a, const float* __restrict__ b,
    const float* __restrict__ lw, const float* __restrict__ lb,
    ushort_t* __restrict__ oh, ushort_t* __restrict__ ol)
{
    int m = blockIdx.x;
    int tid = threadIdx.x;
    const float* ar = a + (size_t)m*C_;
    const float* br = b + (size_t)m*C_;
    float vals[8];
    float s = 0.f, s2 = 0.f;
#pragma unroll
    for (int i = 0; i < 8; i++) {
        int c = tid + 256*i;
        float u = ar[c] + br[c];
        vals[i] = u; s += u; s2 = fmaf(u, u, s2);
    }
#pragma unroll
    for (int o = 16; o > 0; o >>= 1) {
        s  += __shfl_xor_sync(0xffffffffu, s,  o);
        s2 += __shfl_xor_sync(0xffffffffu, s2, o);
    }
    __shared__ float sa[8], sb2[8];
    if ((tid & 31) == 0) { sa[tid>>5] = s; sb2[tid>>5] = s2; }
    __syncthreads();
    s = 0.f; s2 = 0.f;
#pragma unroll
    for (int i = 0; i < 8; i++) { s += sa[i]; s2 += sb2[i]; }
    float mu  = s * (1.0f/C_);
    float var = s2 * (1.0f/C_) - mu*mu;
    float inv = rsqrtf(var + 1e-5f);
#pragma unroll
    for (int i = 0; i < 8; i++) {
        int c = tid + 256*i;
        float v = (vals[i] - mu)*inv*lw[c] + lb[c];
        ushort_t h, l;
        split1(v, h, l);
        oh[(size_t)m*C_ + c] = h;
        ol[(size_t)m*C_ + c] = l;
    }
}

__global__ void copy_xlast(const float* __restrict__ x, float* __restrict__ o)
{
    int i = blockIdx.x*256 + threadIdx.x;
    int b = i >> 11, c = i & (C_-1);
    o[i] = x[((size_t)b*T_ + (T_-1))*C_ + c];
}

// ---------------- launcher ----------------
extern "C" void kernel_launch(void* const* d_in, const int* in_sizes, int n_in,
                              void* d_out, int out_size)
{
    (void)in_sizes; (void)n_in;
    const float* x     = (const float*)d_in[0];
    const float* shift = (const float*)d_in[1];
    const float* wkv0  = (const float*)d_in[2];
    const float* maax  = (const float*)d_in[3];
    const float* maar  = (const float*)d_in[4];
    const float* maak  = (const float*)d_in[5];
    const float* maav  = (const float*)d_in[6];
    const float* maaw  = (const float*)d_in[7];
    const float* maav2 = (const float*)d_in[8];
    const float* w1    = (const float*)d_in[9];
    const float* w2    = (const float*)d_in[10];
    const float* tdec  = (const float*)d_in[11];
    const float* dw1   = (const float*)d_in[12];
    const float* dw2   = (const float*)d_in[13];
    const float* vw1   = (const float*)d_in[14];
    const float* vw2   = (const float*)d_in[15];
    const float* Wr    = (const float*)d_in[17];
    const float* Wk    = (const float*)d_in[18];
    const float* Wv    = (const float*)d_in[19];
    const float* Wo    = (const float*)d_in[20];
    const float* lnw   = (const float*)d_in[21];
    const float* lnb   = (const float*)d_in[22];
    float* out = (float*)d_out;

    float *tm,*xrf,*xkf,*xvf,*xwf,*rb,*kb,*vb,*v2b,*db,*lwv,*lv2,*yw;
    ushort_t *ah,*al,*wr,*wk,*wv,*wo,*w1t;
    cudaGetSymbolAddress((void**)&tm,  g_tm);
    cudaGetSymbolAddress((void**)&xrf, g_xr);
    cudaGetSymbolAddress((void**)&xkf, g_xk);
    cudaGetSymbolAddress((void**)&xvf, g_xv);
    cudaGetSymbolAddress((void**)&xwf, g_xw);
    cudaGetSymbolAddress((void**)&rb,  g_r);
    cudaGetSymbolAddress((void**)&kb,  g_k);
    cudaGetSymbolAddress((void**)&vb,  g_v);
    cudaGetSymbolAddress((void**)&v2b, g_v2);
    cudaGetSymbolAddress((void**)&db,  g_d);
    cudaGetSymbolAddress((void**)&lwv, g_lw);
    cudaGetSymbolAddress((void**)&lv2, g_lv2);
    cudaGetSymbolAddress((void**)&yw,  g_yw);
    cudaGetSymbolAddress((void**)&ah,  g_ah);
    cudaGetSymbolAddress((void**)&al,  g_al);
    cudaGetSymbolAddress((void**)&wr,  g_wr);
    cudaGetSymbolAddress((void**)&wk,  g_wk);
    cudaGetSymbolAddress((void**)&wv,  g_wv);
    cudaGetSymbolAddress((void**)&wo,  g_wo);
    cudaGetSymbolAddress((void**)&w1t, g_w1t);

    // fp32 buffers reinterpreted as fp16 hi/lo pairs
    ushort_t* xrh = (ushort_t*)xrf; ushort_t* xrl = xrh + (size_t)M_*C_;
    ushort_t* xkh = (ushort_t*)xkf; ushort_t* xkl = xkh + (size_t)M_*C_;
    ushort_t* xvh = (ushort_t*)xvf; ushort_t* xvl = xvh + (size_t)M_*C_;
    ushort_t* xwh = (ushort_t*)xwf; ushort_t* xwl = xwh + (size_t)M_*C_;
    // r/k/v buffers reinterpreted as fp16
    __half* rh = (__half*)rb;
    __half* kh = (__half*)kb;
    __half* vh = (__half*)vb;

    cudaFuncSetAttribute(gemm_bf3,  cudaFuncAttributeMaxDynamicSharedMemorySize, GEMM_SMEM);
    cudaFuncSetAttribute(gemm_bf3b, cudaFuncAttributeMaxDynamicSharedMemorySize, GEMM_SMEM);
    cudaFuncSetAttribute(gemm_tanh, cudaFuncAttributeMaxDynamicSharedMemorySize, GEMM_SMEM);

    // 0) weight transposes + fp16 convert
    {
        dim3 gt(C_/32, C_/32);
        wsplit_t<<<gt,256>>>(Wr, wr);
        wsplit_t<<<gt,256>>>(Wk, wk);
        wsplit_t<<<gt,256>>>(Wv, wv);
        wsplit_t<<<gt,256>>>(Wo, wo);
        dim3 g1(256/32, C_/32);
        wsplit160<<<g1,256>>>(w1, w1t);
    }

    // 1) LoRA-5 projection via HMMA: xxx split, then tm = tanh(xxx @ w1)
    {
        const int NS = (int)(((size_t)M_*C_/4) / 256);
        xxx_split<<<NS,256>>>(x, shift, maax, ah, al);
        dim3 gT(1, M_/128);
        gemm_tanh<<<gT,512,GEMM_SMEM>>>(ah, al, w1t, tm);
    }

    // 2) 5-way mix (all outputs fp16 hi/lo; 5 separate launches)
    {
        dim3 g(C_/64, M_/32);
        mix_apply_f<<<g,256>>>(x, shift, tm, w2, maar,  xrh, xrl, 0);
        mix_apply_f<<<g,256>>>(x, shift, tm, w2, maak,  xkh, xkl, 1);
        mix_apply_f<<<g,256>>>(x, shift, tm, w2, maav,  xvh, xvl, 2);
        mix_apply_f<<<g,256>>>(x, shift, tm, w2, maaw,  xwh, xwl, 3);
        mix_apply_f<<<g,256>>>(x, shift, tm, w2, maav2, ah,  al,  4);
    }

    // 3) big projections via batched HMMA fp16x2; r/k/v stored fp16, v2 fp32
    {
        GemmBatch gb;
        gb.Ah[0]=xrh; gb.Al[0]=xrl; gb.Bh[0]=wr; gb.Cm[0]=rh;  gb.half_out[0]=1;
        gb.Ah[1]=xkh; gb.Al[1]=xkl; gb.Bh[1]=wk; gb.Cm[1]=kh;  gb.half_out[1]=1;
        gb.Ah[2]=xvh; gb.Al[2]=xvl; gb.Bh[2]=wv; gb.Cm[2]=vh;  gb.half_out[2]=1;
        gb.Ah[3]=ah;  gb.Al[3]=al;  gb.Bh[3]=wv; gb.Cm[3]=v2b; gb.half_out[3]=0;
        dim3 gb4(C_/256, M_/128, 4);
        gemm_bf3b<<<gb4,512,GEMM_SMEM>>>(gb);
    }

    // 4) decay / value2 LoRAs (split-input skinny) + smallK epilogues
    skinny64_split<<<M_/64, 256>>>(xwh, xwl, dw1, lwv);
    skinny64_split<<<M_/64, 256>>>(ah,  al,  vw1, lv2);
    {
        dim3 gs(C_/128, M_/32);
        smallk_gemm<0><<<gs,256>>>(lwv, dw2, tdec, db);      // d only
        smallk_gemm<1><<<gs,256>>>(lv2, vw2, nullptr, v2b);  // v2 += lora
    }

    // 5) WKV scan (fp16 r/k/v), 6) LN, 7) output projection
    const size_t OFFS = (size_t)M_*C_;
    const size_t OFFX = OFFS + (size_t)B_*H_*HS_*HS_;
    bool full = (size_t)out_size >= OFFX + (size_t)B_*C_;
    float* Sout = full ? (out + OFFS) : tm;
    wkv_scan<<<B_*H_, 64>>>(rh, kh, vh, db, wkv0, yw, Sout);
    ln_add_split<<<M_, 256>>>(yw, v2b, lnw, lnb, ah, al);
    dim3 gg(C_/256, M_/128);
    gemm_bf3<<<gg,512,GEMM_SMEM>>>(ah, al, wo, out);
    if (full) copy_xlast<<<(B_*C_)/256, 256>>>(x, out + OFFX);
}